// round 1
// baseline (speedup 1.0000x reference)
#include <cuda_runtime.h>
#include <math.h>

#define NU 100000
#define NI 50000
#define DIMV 64
#define RK 5
#define NNZE 2000000
#define NUID 2048
#define NIID 4096

// ---------------- device scratch (no allocations allowed) ----------------
__device__ __align__(16) float g_Eu0[NU*DIMV];
__device__ __align__(16) float g_Ei0[NI*DIMV];
__device__ __align__(16) float g_Zu1[NU*DIMV];
__device__ __align__(16) float g_Zi1[NI*DIMV];
__device__ __align__(16) float g_Eu [NU*DIMV];
__device__ __align__(16) float g_Ei [NI*DIMV];
__device__ __align__(16) float g_Gu [NU*DIMV];
__device__ __align__(16) float g_Gi [NI*DIMV];
__device__ float g_P1[RK*DIMV];
__device__ float g_P2[RK*DIMV];
__device__ int   g_rcnt[NU];
__device__ int   g_rbase[NU];
__device__ int   g_rfill[NU];
__device__ int   g_ccnt[NI];
__device__ int   g_cbase[NI];
__device__ int   g_cfill[NI];
__device__ int   g_rcols[NNZE];
__device__ float g_rvals[NNZE];
__device__ int   g_crows[NNZE];
__device__ float g_cvals[NNZE];
__device__ int   g_bsU[128];
__device__ int   g_bsI[128];
__device__ float g_sumU[NUID];
__device__ float g_sumI[NIID];
__device__ float g_scal[8];

// ---------------- kernels ----------------

__global__ void k_zero(int* rcnt,int* rfill,int* ccnt,int* cfill,
                       float* P1,float* P2,float* sumU,float* sumI,float* scal){
    int i = blockIdx.x*256 + threadIdx.x;
    if (i < NU){ rcnt[i]=0; rfill[i]=0; }
    if (i < NI){ ccnt[i]=0; cfill[i]=0; }
    if (i < NUID) sumU[i]=0.f;
    if (i < NIID) sumI[i]=0.f;
    if (i < RK*DIMV){ P1[i]=0.f; P2[i]=0.f; }
    if (i < 8) scal[i]=0.f;
}

__global__ void k_init(const float4* __restrict__ ue, const float4* __restrict__ uep,
                       const float4* __restrict__ ie, const float4* __restrict__ iep,
                       float4* __restrict__ Eu0, float4* __restrict__ Ei0){
    int i = blockIdx.x*256 + threadIdx.x;
    if (i < NU*16){
        float4 a = ue[i], b = uep[i];
        Eu0[i] = make_float4(a.x+b.x, a.y+b.y, a.z+b.z, a.w+b.w);
    } else if (i < (NU+NI)*16){
        int k = i - NU*16;
        float4 a = ie[k], b = iep[k];
        Ei0[k] = make_float4(a.x+b.x, a.y+b.y, a.z+b.z, a.w+b.w);
    }
}

__global__ void k_count(const int* __restrict__ rows, const int* __restrict__ cols,
                        int* rcnt, int* ccnt){
    int e = blockIdx.x*256 + threadIdx.x;
    if (e < NNZE){
        atomicAdd(&rcnt[rows[e]], 1);
        atomicAdd(&ccnt[cols[e]], 1);
    }
}

__global__ void k_scan_block(const int* __restrict__ cnt, int n, int* base, int* bsums){
    __shared__ int sh[1024];
    int i = blockIdx.x*1024 + threadIdx.x;
    int v = (i < n) ? cnt[i] : 0;
    sh[threadIdx.x] = v;
    __syncthreads();
    for (int off=1; off<1024; off<<=1){
        int t = (threadIdx.x >= off) ? sh[threadIdx.x-off] : 0;
        __syncthreads();
        sh[threadIdx.x] += t;
        __syncthreads();
    }
    if (i < n) base[i] = sh[threadIdx.x] - v;
    if (threadIdx.x == 1023) bsums[blockIdx.x] = sh[1023];
}

__global__ void k_scan_top(int* bsums, int nb){
    __shared__ int sh[128];
    int tid = threadIdx.x;
    int v = (tid < nb) ? bsums[tid] : 0;
    sh[tid] = v;
    __syncthreads();
    for (int off=1; off<128; off<<=1){
        int t = (tid >= off) ? sh[tid-off] : 0;
        __syncthreads();
        sh[tid] += t;
        __syncthreads();
    }
    if (tid < nb) bsums[tid] = sh[tid] - v;
}

__global__ void k_scan_add(int* base, int n, const int* __restrict__ bsums){
    int i = blockIdx.x*1024 + threadIdx.x;
    if (i < n) base[i] += bsums[i >> 10];
}

__global__ void k_scatter(const int* __restrict__ rows, const int* __restrict__ cols,
                          const float* __restrict__ vals,
                          const int* __restrict__ rbase, int* rfill, int* rcols, float* rvals,
                          const int* __restrict__ cbase, int* cfill, int* crows, float* cvals){
    int e = blockIdx.x*256 + threadIdx.x;
    if (e < NNZE){
        int r = rows[e], c = cols[e];
        float v = vals[e];
        int pr = rbase[r] + atomicAdd(&rfill[r], 1);
        rcols[pr] = c; rvals[pr] = v;
        int pc = cbase[c] + atomicAdd(&cfill[c], 1);
        crows[pc] = r; cvals[pc] = v;
    }
}

// gather-style SpMM: dst[row] = (sum_e v*src[nbr] + add0[row] + add1[row]) * scale
__global__ void k_spmm(const int* __restrict__ base, const int* __restrict__ cnt,
                       const int* __restrict__ nbr, const float* __restrict__ nvals,
                       const float* __restrict__ src,
                       const float* __restrict__ add0, const float* __restrict__ add1,
                       float scale, float* __restrict__ dst, int nrows){
    int row = blockIdx.x*16 + (threadIdx.x >> 4);
    int lane = threadIdx.x & 15;
    if (row >= nrows) return;
    int s = base[row], n = cnt[row];
    float4 acc = make_float4(0.f,0.f,0.f,0.f);
    for (int p=0; p<n; p++){
        int j = nbr[s+p];
        float v = nvals[s+p];
        float4 x = ((const float4*)src)[(size_t)j*16 + lane];
        acc.x = fmaf(v, x.x, acc.x);
        acc.y = fmaf(v, x.y, acc.y);
        acc.z = fmaf(v, x.z, acc.z);
        acc.w = fmaf(v, x.w, acc.w);
    }
    size_t o = (size_t)row*16 + lane;
    if (add0){ float4 a = ((const float4*)add0)[o]; acc.x+=a.x; acc.y+=a.y; acc.z+=a.z; acc.w+=a.w; }
    if (add1){ float4 a = ((const float4*)add1)[o]; acc.x+=a.x; acc.y+=a.y; acc.z+=a.z; acc.w+=a.w; }
    acc.x*=scale; acc.y*=scale; acc.z*=scale; acc.w*=scale;
    ((float4*)dst)[o] = acc;
}

// P[r][d] += sum_i fac[r*n+i] * (A[i][d] + B[i][d])
__global__ void k_lowrank(const float* __restrict__ fac, const float* __restrict__ A,
                          const float* __restrict__ B, float* __restrict__ P, int n){
    int d  = threadIdx.x & 63;
    int il = threadIdx.x >> 6;   // 0..3
    int chunk = (n + gridDim.x - 1) / gridDim.x;
    int i0 = blockIdx.x*chunk;
    int i1 = min(i0 + chunk, n);
    float acc[RK];
    #pragma unroll
    for (int r=0;r<RK;r++) acc[r]=0.f;
    for (int i=i0+il; i<i1; i+=4){
        float m = A[(size_t)i*DIMV + d] + B[(size_t)i*DIMV + d];
        #pragma unroll
        for (int r=0;r<RK;r++) acc[r] = fmaf(fac[(size_t)r*n + i], m, acc[r]);
    }
    __shared__ float red[4][RK][DIMV];
    #pragma unroll
    for (int r=0;r<RK;r++) red[il][r][d] = acc[r];
    __syncthreads();
    if (il == 0){
        #pragma unroll
        for (int r=0;r<RK;r++){
            float t = red[0][r][d] + red[1][r][d] + red[2][r][d] + red[3][r][d];
            atomicAdd(&P[r*DIMV + d], t);
        }
    }
}

// out[i] = (base0[i] + sum_r muls[u][r]*P[r][d]) / 3
__global__ void k_gmix(const float* __restrict__ base0, const float* __restrict__ muls,
                       const float* __restrict__ P, float* __restrict__ out, int total){
    int i = blockIdx.x*256 + threadIdx.x;
    if (i >= total) return;
    int u = i >> 6, d = i & 63;
    float s = base0[i];
    #pragma unroll
    for (int r=0;r<RK;r++) s = fmaf(muls[(size_t)u*RK + r], P[r*DIMV + d], s);
    out[i] = s * (1.0f/3.0f);
}

// fused GEMM + exp-sum: sums[k] += sum_j exp(dot(G[ids[k]], E[j]) / T)
// block: 16 ids x 256 cols; thread: 4 ids x 4 cols register tile; swizzled smem
__global__ void k_neg(const float* __restrict__ G, const float* __restrict__ E,
                      const int* __restrict__ ids, int NJ, float* __restrict__ sums){
    extern __shared__ float4 Es[];     // 256 rows x 16 float4, XOR-swizzled
    __shared__ float4 Gs[256];         // 16 ids x 16 float4
    int tid = threadIdx.x;
    {
        int t = tid >> 4, d4 = tid & 15;
        int k = ids[blockIdx.x*16 + t];
        Gs[tid] = ((const float4*)G)[(size_t)k*16 + d4];
    }
    int jbase = blockIdx.y * 256;
    #pragma unroll
    for (int kk=0; kk<16; kk++){
        int k = kk*256 + tid;
        int j = k >> 4, d4 = k & 15;
        float4 v = make_float4(0.f,0.f,0.f,0.f);
        int jg = jbase + j;
        if (jg < NJ) v = ((const float4*)E)[(size_t)jg*16 + d4];
        Es[(j<<4) + (d4 ^ (j & 7))] = v;
    }
    __syncthreads();

    int ty = tid >> 6;      // id group (4 ids)
    int tx = tid & 63;      // col lane (4 cols strided by 64)
    float acc[4][4];
    #pragma unroll
    for (int u=0;u<4;u++)
        #pragma unroll
        for (int jj=0;jj<4;jj++) acc[u][jj]=0.f;

    #pragma unroll 4
    for (int d4=0; d4<16; d4++){
        float4 gv[4], ev[4];
        #pragma unroll
        for (int u=0;u<4;u++) gv[u] = Gs[((ty*4+u)<<4) + d4];
        #pragma unroll
        for (int jj=0;jj<4;jj++){
            int jl = tx + (jj<<6);
            ev[jj] = Es[(jl<<4) + (d4 ^ (jl & 7))];
        }
        #pragma unroll
        for (int u=0;u<4;u++)
            #pragma unroll
            for (int jj=0;jj<4;jj++){
                acc[u][jj] = fmaf(gv[u].x, ev[jj].x, acc[u][jj]);
                acc[u][jj] = fmaf(gv[u].y, ev[jj].y, acc[u][jj]);
                acc[u][jj] = fmaf(gv[u].z, ev[jj].z, acc[u][jj]);
                acc[u][jj] = fmaf(gv[u].w, ev[jj].w, acc[u][jj]);
            }
    }
    float s[4] = {0.f,0.f,0.f,0.f};
    #pragma unroll
    for (int jj=0;jj<4;jj++){
        if (jbase + tx + (jj<<6) < NJ){
            #pragma unroll
            for (int u=0;u<4;u++) s[u] += __expf(acc[u][jj] * 5.0f);  // 1/TEMP = 5
        }
    }
    #pragma unroll
    for (int u=0;u<4;u++)
        for (int off=16; off>0; off>>=1) s[u] += __shfl_xor_sync(0xffffffffu, s[u], off);
    if ((tid & 31) == 0){
        #pragma unroll
        for (int u=0;u<4;u++) atomicAdd(&sums[blockIdx.x*16 + ty*4 + u], s[u]);
    }
}

__global__ void k_pos(const float* __restrict__ Gu, const float* __restrict__ Eu,
                      const float* __restrict__ Gi, const float* __restrict__ Ei,
                      const int* __restrict__ uids, const int* __restrict__ iids,
                      float* scal){
    int w = (blockIdx.x*blockDim.x + threadIdx.x) >> 5;
    int lane = threadIdx.x & 31;
    if (w >= NUID + NIID) return;
    const float *g, *e; int slot;
    if (w < NUID){ int k = uids[w];      g = Gu + (size_t)k*DIMV; e = Eu + (size_t)k*DIMV; slot=0; }
    else         { int k = iids[w-NUID]; g = Gi + (size_t)k*DIMV; e = Ei + (size_t)k*DIMV; slot=1; }
    float2 a = ((const float2*)g)[lane];
    float2 b = ((const float2*)e)[lane];
    float d = a.x*b.x + a.y*b.y;
    for (int off=16; off>0; off>>=1) d += __shfl_xor_sync(0xffffffffu, d, off);
    if (lane == 0){
        float v = fminf(fmaxf(d*5.0f, -5.0f), 5.0f);
        atomicAdd(&scal[slot], v);
    }
}

__global__ void k_out(const float* __restrict__ Eu, const float* __restrict__ Ei,
                      const float* __restrict__ iu, const float* __restrict__ tu,
                      const float* __restrict__ ii, const float* __restrict__ ti,
                      float* __restrict__ out){
    int row = blockIdx.x*8 + (threadIdx.x >> 5);
    int lane = threadIdx.x & 31;
    const float *e, *a, *b; float* o;
    if (row < NU){
        e = Eu + (size_t)row*DIMV; a = iu + (size_t)row*DIMV; b = tu + (size_t)row*DIMV;
        o = out + (size_t)row*DIMV;
    } else {
        int r = row - NU;
        e = Ei + (size_t)r*DIMV; a = ii + (size_t)r*DIMV; b = ti + (size_t)r*DIMV;
        o = out + (size_t)NU*DIMV + (size_t)r*DIMV;
    }
    float2 e2 = ((const float2*)e)[lane];
    float2 a2 = ((const float2*)a)[lane];
    float2 b2 = ((const float2*)b)[lane];
    float sa = a2.x*a2.x + a2.y*a2.y;
    float sb = b2.x*b2.x + b2.y*b2.y;
    for (int off=16; off>0; off>>=1){
        sa += __shfl_xor_sync(0xffffffffu, sa, off);
        sb += __shfl_xor_sync(0xffffffffu, sb, off);
    }
    float na = fmaxf(sqrtf(sa), 1e-12f);
    float nb = fmaxf(sqrtf(sb), 1e-12f);
    float2 r2;
    r2.x = e2.x + 0.02f*(a2.x/na) + 0.02f*(b2.x/nb);
    r2.y = e2.y + 0.02f*(a2.y/na) + 0.02f*(b2.y/nb);
    ((float2*)o)[lane] = r2;
}

__global__ void k_loss(const float* __restrict__ sumU, const float* __restrict__ sumI,
                       const float* __restrict__ scal, float* outp){
    __shared__ float sh[256];
    int tid = threadIdx.x;
    float acc = 0.f;
    for (int k=tid; k<NUID; k+=256) acc += logf(sumU[k]) * (1.0f/NUID);
    for (int k=tid; k<NIID; k+=256) acc += logf(sumI[k]) * (1.0f/NIID);
    sh[tid] = acc;
    __syncthreads();
    for (int off=128; off>0; off>>=1){
        if (tid < off) sh[tid] += sh[tid+off];
        __syncthreads();
    }
    if (tid == 0){
        float neg = sh[0];
        float pos = scal[0]*(1.0f/NUID) + scal[1]*(1.0f/NIID);
        outp[0] = (neg - pos) * 4.0f;   // * (len(G_u_list)+1)
    }
}

// ---------------- launcher ----------------
extern "C" void kernel_launch(void* const* d_in, const int* in_sizes, int n_in,
                              void* d_out, int out_size){
    const float* user_emb     = (const float*)d_in[0];
    const float* item_emb     = (const float*)d_in[1];
    const float* user_emb_pre = (const float*)d_in[2];
    const float* item_emb_pre = (const float*)d_in[3];
    const float* img_item     = (const float*)d_in[4];
    const float* txt_item     = (const float*)d_in[5];
    const float* img_user     = (const float*)d_in[6];
    const float* txt_user     = (const float*)d_in[7];
    const int*   arows        = (const int*)d_in[8];
    const int*   acols        = (const int*)d_in[9];
    const float* avals        = (const float*)d_in[10];
    const float* ut           = (const float*)d_in[11];
    const float* vt           = (const float*)d_in[12];
    const float* u_mul_s      = (const float*)d_in[13];
    const float* v_mul_s      = (const float*)d_in[14];
    const int*   uids         = (const int*)d_in[15];
    const int*   iids         = (const int*)d_in[16];
    float* out = (float*)d_out;

    float *Eu0,*Ei0,*Zu1,*Zi1,*Eu,*Ei,*Gu,*Gi,*P1,*P2,*sumU,*sumI,*scal,*rvals,*cvals;
    int *rcnt,*rbase,*rfill,*ccnt,*cbase,*cfill,*rcols,*crows,*bsU,*bsI;
    cudaGetSymbolAddress((void**)&Eu0,  g_Eu0);
    cudaGetSymbolAddress((void**)&Ei0,  g_Ei0);
    cudaGetSymbolAddress((void**)&Zu1,  g_Zu1);
    cudaGetSymbolAddress((void**)&Zi1,  g_Zi1);
    cudaGetSymbolAddress((void**)&Eu,   g_Eu);
    cudaGetSymbolAddress((void**)&Ei,   g_Ei);
    cudaGetSymbolAddress((void**)&Gu,   g_Gu);
    cudaGetSymbolAddress((void**)&Gi,   g_Gi);
    cudaGetSymbolAddress((void**)&P1,   g_P1);
    cudaGetSymbolAddress((void**)&P2,   g_P2);
    cudaGetSymbolAddress((void**)&sumU, g_sumU);
    cudaGetSymbolAddress((void**)&sumI, g_sumI);
    cudaGetSymbolAddress((void**)&scal, g_scal);
    cudaGetSymbolAddress((void**)&rcnt, g_rcnt);
    cudaGetSymbolAddress((void**)&rbase,g_rbase);
    cudaGetSymbolAddress((void**)&rfill,g_rfill);
    cudaGetSymbolAddress((void**)&ccnt, g_ccnt);
    cudaGetSymbolAddress((void**)&cbase,g_cbase);
    cudaGetSymbolAddress((void**)&cfill,g_cfill);
    cudaGetSymbolAddress((void**)&rcols,g_rcols);
    cudaGetSymbolAddress((void**)&rvals,g_rvals);
    cudaGetSymbolAddress((void**)&crows,g_crows);
    cudaGetSymbolAddress((void**)&cvals,g_cvals);
    cudaGetSymbolAddress((void**)&bsU,  g_bsU);
    cudaGetSymbolAddress((void**)&bsI,  g_bsI);

    cudaFuncSetAttribute(k_neg, cudaFuncAttributeMaxDynamicSharedMemorySize, 65536);

    // init + CSR/CSC build
    k_zero<<<(NU+255)/256, 256>>>(rcnt,rfill,ccnt,cfill,P1,P2,sumU,sumI,scal);
    k_init<<<((NU+NI)*16+255)/256, 256>>>((const float4*)user_emb,(const float4*)user_emb_pre,
                                          (const float4*)item_emb,(const float4*)item_emb_pre,
                                          (float4*)Eu0,(float4*)Ei0);
    k_count<<<(NNZE+255)/256, 256>>>(arows, acols, rcnt, ccnt);
    k_scan_block<<<98, 1024>>>(rcnt, NU, rbase, bsU);
    k_scan_top<<<1, 128>>>(bsU, 98);
    k_scan_add<<<98, 1024>>>(rbase, NU, bsU);
    k_scan_block<<<49, 1024>>>(ccnt, NI, cbase, bsI);
    k_scan_top<<<1, 128>>>(bsI, 49);
    k_scan_add<<<49, 1024>>>(cbase, NI, bsI);
    k_scatter<<<(NNZE+255)/256, 256>>>(arows,acols,avals, rbase,rfill,rcols,rvals,
                                       cbase,cfill,crows,cvals);

    // GNN layer 1
    k_spmm<<<NU/16, 256>>>(rbase,rcnt,rcols,rvals, Ei0, nullptr,nullptr, 1.0f, Zu1, NU);
    k_spmm<<<NI/16, 256>>>(cbase,ccnt,crows,cvals, Eu0, nullptr,nullptr, 1.0f, Zi1, NI);
    // GNN layer 2 fused with averaging: E = (E0 + Z1 + Z2)/3
    k_spmm<<<NU/16, 256>>>(rbase,rcnt,rcols,rvals, Zi1, Eu0, Zu1, 1.0f/3.0f, Eu, NU);
    k_spmm<<<NI/16, 256>>>(cbase,ccnt,crows,cvals, Zu1, Ei0, Zi1, 1.0f/3.0f, Ei, NI);

    // low-rank SVD path: G = (E0 + muls @ (fac @ (E0_other + Z1_other)))/3
    k_lowrank<<<128, 256>>>(vt, Ei0, Zi1, P1, NI);
    k_lowrank<<<128, 256>>>(ut, Eu0, Zu1, P2, NU);
    k_gmix<<<(NU*DIMV)/256, 256>>>(Eu0, u_mul_s, P1, Gu, NU*DIMV);
    k_gmix<<<(NI*DIMV)/256, 256>>>(Ei0, v_mul_s, P2, Gi, NI*DIMV);

    // contrastive loss pieces
    k_neg<<<dim3(NUID/16, (NU+255)/256), 256, 65536>>>(Gu, Eu, uids, NU, sumU);
    k_neg<<<dim3(NIID/16, (NI+255)/256), 256, 65536>>>(Gi, Ei, iids, NI, sumI);
    k_pos<<<(NUID+NIID)/8, 256>>>(Gu, Eu, Gi, Ei, uids, iids, scal);

    // outputs
    k_out<<<(NU+NI)/8, 256>>>(Eu, Ei, img_user, txt_user, img_item, txt_item, out);
    k_loss<<<1, 256>>>(sumU, sumI, scal, out + (size_t)(NU+NI)*DIMV);
}

// round 2
// speedup vs baseline: 2.7556x; 2.7556x over previous
#include <cuda_runtime.h>
#include <cuda_bf16.h>
#include <math.h>

#define NU 100000
#define NI 50000
#define DIMV 64
#define RK 5
#define NNZE 2000000
#define NUID 2048
#define NIID 4096

// ---------------- device scratch (no allocations allowed) ----------------
__device__ __align__(16) float g_Eu0[NU*DIMV];
__device__ __align__(16) float g_Ei0[NI*DIMV];
__device__ __align__(16) float g_Zu1[NU*DIMV];
__device__ __align__(16) float g_Zi1[NI*DIMV];
__device__ __align__(16) float g_Eu [NU*DIMV];
__device__ __align__(16) float g_Ei [NI*DIMV];
__device__ __align__(16) __nv_bfloat16 g_EbfU[NU*DIMV];
__device__ __align__(16) __nv_bfloat16 g_EbfI[NI*DIMV];
__device__ __align__(16) float g_GselU[NUID*DIMV];
__device__ __align__(16) float g_GselI[NIID*DIMV];
__device__ __align__(16) __nv_bfloat16 g_AbfU[NUID*DIMV];
__device__ __align__(16) __nv_bfloat16 g_AbfI[NIID*DIMV];
__device__ float g_P1[RK*DIMV];
__device__ float g_P2[RK*DIMV];
__device__ int   g_rcnt[NU];
__device__ int   g_rbase[NU];
__device__ int   g_rfill[NU];
__device__ int   g_ccnt[NI];
__device__ int   g_cbase[NI];
__device__ int   g_cfill[NI];
__device__ int   g_rcols[NNZE];
__device__ float g_rvals[NNZE];
__device__ int   g_crows[NNZE];
__device__ float g_cvals[NNZE];
__device__ int   g_bsU[128];
__device__ int   g_bsI[128];
__device__ float g_sumU[NUID];
__device__ float g_sumI[NIID];
__device__ float g_scal[8];

// ---------------- kernels ----------------

__global__ void k_zero(int* rcnt,int* rfill,int* ccnt,int* cfill,
                       float* P1,float* P2,float* sumU,float* sumI,float* scal){
    int i = blockIdx.x*256 + threadIdx.x;
    if (i < NU){ rcnt[i]=0; rfill[i]=0; }
    if (i < NI){ ccnt[i]=0; cfill[i]=0; }
    if (i < NUID) sumU[i]=0.f;
    if (i < NIID) sumI[i]=0.f;
    if (i < RK*DIMV){ P1[i]=0.f; P2[i]=0.f; }
    if (i < 8) scal[i]=0.f;
}

__global__ void k_init(const float4* __restrict__ ue, const float4* __restrict__ uep,
                       const float4* __restrict__ ie, const float4* __restrict__ iep,
                       float4* __restrict__ Eu0, float4* __restrict__ Ei0){
    int i = blockIdx.x*256 + threadIdx.x;
    if (i < NU*16){
        float4 a = ue[i], b = uep[i];
        Eu0[i] = make_float4(a.x+b.x, a.y+b.y, a.z+b.z, a.w+b.w);
    } else if (i < (NU+NI)*16){
        int k = i - NU*16;
        float4 a = ie[k], b = iep[k];
        Ei0[k] = make_float4(a.x+b.x, a.y+b.y, a.z+b.z, a.w+b.w);
    }
}

__global__ void k_count(const int* __restrict__ rows, const int* __restrict__ cols,
                        int* rcnt, int* ccnt){
    int e = blockIdx.x*256 + threadIdx.x;
    if (e < NNZE){
        atomicAdd(&rcnt[rows[e]], 1);
        atomicAdd(&ccnt[cols[e]], 1);
    }
}

__global__ void k_scan_block(const int* __restrict__ cnt, int n, int* base, int* bsums){
    __shared__ int sh[1024];
    int i = blockIdx.x*1024 + threadIdx.x;
    int v = (i < n) ? cnt[i] : 0;
    sh[threadIdx.x] = v;
    __syncthreads();
    for (int off=1; off<1024; off<<=1){
        int t = (threadIdx.x >= off) ? sh[threadIdx.x-off] : 0;
        __syncthreads();
        sh[threadIdx.x] += t;
        __syncthreads();
    }
    if (i < n) base[i] = sh[threadIdx.x] - v;
    if (threadIdx.x == 1023) bsums[blockIdx.x] = sh[1023];
}

__global__ void k_scan_top(int* bsums, int nb){
    __shared__ int sh[128];
    int tid = threadIdx.x;
    int v = (tid < nb) ? bsums[tid] : 0;
    sh[tid] = v;
    __syncthreads();
    for (int off=1; off<128; off<<=1){
        int t = (tid >= off) ? sh[tid-off] : 0;
        __syncthreads();
        sh[tid] += t;
        __syncthreads();
    }
    if (tid < nb) bsums[tid] = sh[tid] - v;
}

__global__ void k_scan_add(int* base, int n, const int* __restrict__ bsums){
    int i = blockIdx.x*1024 + threadIdx.x;
    if (i < n) base[i] += bsums[i >> 10];
}

__global__ void k_scatter(const int* __restrict__ rows, const int* __restrict__ cols,
                          const float* __restrict__ vals,
                          const int* __restrict__ rbase, int* rfill, int* rcols, float* rvals,
                          const int* __restrict__ cbase, int* cfill, int* crows, float* cvals){
    int e = blockIdx.x*256 + threadIdx.x;
    if (e < NNZE){
        int r = rows[e], c = cols[e];
        float v = vals[e];
        int pr = rbase[r] + atomicAdd(&rfill[r], 1);
        rcols[pr] = c; rvals[pr] = v;
        int pc = cbase[c] + atomicAdd(&cfill[c], 1);
        crows[pc] = r; cvals[pc] = v;
    }
}

// gather-style SpMM: dst[row] = (sum_e v*src[nbr] + add0[row] + add1[row]) * scale
// optionally also emits bf16 copy of dst
__global__ void k_spmm(const int* __restrict__ base, const int* __restrict__ cnt,
                       const int* __restrict__ nbr, const float* __restrict__ nvals,
                       const float* __restrict__ src,
                       const float* __restrict__ add0, const float* __restrict__ add1,
                       float scale, float* __restrict__ dst,
                       __nv_bfloat16* __restrict__ bdst, int nrows){
    int row = blockIdx.x*16 + (threadIdx.x >> 4);
    int lane = threadIdx.x & 15;
    if (row >= nrows) return;
    int s = base[row], n = cnt[row];
    float4 acc = make_float4(0.f,0.f,0.f,0.f);
    for (int p=0; p<n; p++){
        int j = nbr[s+p];
        float v = nvals[s+p];
        float4 x = ((const float4*)src)[(size_t)j*16 + lane];
        acc.x = fmaf(v, x.x, acc.x);
        acc.y = fmaf(v, x.y, acc.y);
        acc.z = fmaf(v, x.z, acc.z);
        acc.w = fmaf(v, x.w, acc.w);
    }
    size_t o = (size_t)row*16 + lane;
    if (add0){ float4 a = ((const float4*)add0)[o]; acc.x+=a.x; acc.y+=a.y; acc.z+=a.z; acc.w+=a.w; }
    if (add1){ float4 a = ((const float4*)add1)[o]; acc.x+=a.x; acc.y+=a.y; acc.z+=a.z; acc.w+=a.w; }
    acc.x*=scale; acc.y*=scale; acc.z*=scale; acc.w*=scale;
    ((float4*)dst)[o] = acc;
    if (bdst){
        __nv_bfloat162 b0 = __floats2bfloat162_rn(acc.x, acc.y);
        __nv_bfloat162 b1 = __floats2bfloat162_rn(acc.z, acc.w);
        ((__nv_bfloat162*)bdst)[o*2+0] = b0;
        ((__nv_bfloat162*)bdst)[o*2+1] = b1;
    }
}

// P[r][d] += sum_i fac[r*n+i] * (A[i][d] + B[i][d])
__global__ void k_lowrank(const float* __restrict__ fac, const float* __restrict__ A,
                          const float* __restrict__ B, float* __restrict__ P, int n){
    int d  = threadIdx.x & 63;
    int il = threadIdx.x >> 6;   // 0..3
    int chunk = (n + gridDim.x - 1) / gridDim.x;
    int i0 = blockIdx.x*chunk;
    int i1 = min(i0 + chunk, n);
    float acc[RK];
    #pragma unroll
    for (int r=0;r<RK;r++) acc[r]=0.f;
    for (int i=i0+il; i<i1; i+=4){
        float m = A[(size_t)i*DIMV + d] + B[(size_t)i*DIMV + d];
        #pragma unroll
        for (int r=0;r<RK;r++) acc[r] = fmaf(fac[(size_t)r*n + i], m, acc[r]);
    }
    __shared__ float red[4][RK][DIMV];
    #pragma unroll
    for (int r=0;r<RK;r++) red[il][r][d] = acc[r];
    __syncthreads();
    if (il == 0){
        #pragma unroll
        for (int r=0;r<RK;r++){
            float t = red[0][r][d] + red[1][r][d] + red[2][r][d] + red[3][r][d];
            atomicAdd(&P[r*DIMV + d], t);
        }
    }
}

// gathered G rows only: Gsel[w] = (E0[id] + muls[id] @ P)/3 ; Abf = bf16(Gsel * 5*log2e)
__global__ void k_gsel(const int* __restrict__ ids, const float* __restrict__ base0,
                       const float* __restrict__ muls, const float* __restrict__ P,
                       float* __restrict__ Gsel, __nv_bfloat16* __restrict__ Abf, int nids){
    int i = blockIdx.x*256 + threadIdx.x;
    if (i >= nids*DIMV) return;
    int w = i >> 6, d = i & 63;
    int id = ids[w];
    float s = base0[(size_t)id*DIMV + d];
    #pragma unroll
    for (int r=0;r<RK;r++) s = fmaf(muls[(size_t)id*RK + r], P[r*DIMV + d], s);
    s *= (1.0f/3.0f);
    Gsel[i] = s;
    Abf[i] = __float2bfloat16(s * 7.2134752044448170f);  // (1/T) * log2(e) = 5*1.442695...
}

__device__ __forceinline__ float ex2f(float x){
    float r;
    asm("ex2.approx.f32 %0, %1;" : "=f"(r) : "f"(x));
    return r;
}

// sums[m0+r] += sum_j exp2( dot(Abf[m0+r], Ebf[j]) )   (scale pre-folded into A)
// CTA tile: 64 ids x 128 cols, K=64 single shot. 8 warps = 2(M) x 4(N).
__global__ void __launch_bounds__(256) k_negmma(
        const __nv_bfloat16* __restrict__ A, const __nv_bfloat16* __restrict__ E,
        int NJ, float* __restrict__ sums){
    __shared__ __nv_bfloat16 As[64][72];
    __shared__ __nv_bfloat16 Bs[128][72];
    __shared__ float ls[64];
    int tid = threadIdx.x;
    int m0 = blockIdx.y * 64;
    int jbase = blockIdx.x * 128;
    if (tid < 64) ls[tid] = 0.f;

    // load A tile (64x64 bf16) as 16B chunks
    #pragma unroll
    for (int c = tid; c < 512; c += 256){
        int r = c >> 3, c8 = c & 7;
        uint4 v = *(const uint4*)(A + (size_t)(m0 + r)*DIMV + c8*8);
        *(uint4*)&As[r][c8*8] = v;
    }
    // load B tile (128x64 bf16), zero-padded past NJ
    #pragma unroll
    for (int c = tid; c < 1024; c += 256){
        int r = c >> 3, c8 = c & 7;
        int j = jbase + r;
        uint4 v = make_uint4(0u,0u,0u,0u);
        if (j < NJ) v = *(const uint4*)(E + (size_t)j*DIMV + c8*8);
        *(uint4*)&Bs[r][c8*8] = v;
    }
    __syncthreads();

    int warp = tid >> 5, lane = tid & 31;
    int wm = warp >> 2, wn = warp & 3;
    int g = lane >> 2, t = lane & 3;

    float acc[2][4][4];
    #pragma unroll
    for (int mf=0;mf<2;mf++)
        #pragma unroll
        for (int nf=0;nf<4;nf++)
            #pragma unroll
            for (int q=0;q<4;q++) acc[mf][nf][q]=0.f;

    #pragma unroll
    for (int kk=0; kk<4; kk++){
        int kb = kk*16 + 2*t;
        unsigned a[2][4], b[4][2];
        #pragma unroll
        for (int mf=0; mf<2; mf++){
            int r = wm*32 + mf*16 + g;
            a[mf][0] = *(const unsigned*)&As[r  ][kb  ];
            a[mf][1] = *(const unsigned*)&As[r+8][kb  ];
            a[mf][2] = *(const unsigned*)&As[r  ][kb+8];
            a[mf][3] = *(const unsigned*)&As[r+8][kb+8];
        }
        #pragma unroll
        for (int nf=0; nf<4; nf++){
            int n = wn*32 + nf*8 + g;
            b[nf][0] = *(const unsigned*)&Bs[n][kb  ];
            b[nf][1] = *(const unsigned*)&Bs[n][kb+8];
        }
        #pragma unroll
        for (int mf=0; mf<2; mf++)
            #pragma unroll
            for (int nf=0; nf<4; nf++)
                asm volatile(
                    "mma.sync.aligned.m16n8k16.row.col.f32.bf16.bf16.f32 "
                    "{%0,%1,%2,%3}, {%4,%5,%6,%7}, {%8,%9}, {%0,%1,%2,%3};"
                    : "+f"(acc[mf][nf][0]), "+f"(acc[mf][nf][1]),
                      "+f"(acc[mf][nf][2]), "+f"(acc[mf][nf][3])
                    : "r"(a[mf][0]), "r"(a[mf][1]), "r"(a[mf][2]), "r"(a[mf][3]),
                      "r"(b[nf][0]), "r"(b[nf][1]));
    }

    // epilogue: exp2 + masked sum per row
    #pragma unroll
    for (int mf=0; mf<2; mf++){
        float s0 = 0.f, s1 = 0.f;
        #pragma unroll
        for (int nf=0; nf<4; nf++){
            int jc = jbase + wn*32 + nf*8 + 2*t;
            bool v0 = jc < NJ, v1 = (jc+1) < NJ;
            s0 += (v0 ? ex2f(acc[mf][nf][0]) : 0.f) + (v1 ? ex2f(acc[mf][nf][1]) : 0.f);
            s1 += (v0 ? ex2f(acc[mf][nf][2]) : 0.f) + (v1 ? ex2f(acc[mf][nf][3]) : 0.f);
        }
        s0 += __shfl_xor_sync(0xffffffffu, s0, 1);
        s0 += __shfl_xor_sync(0xffffffffu, s0, 2);
        s1 += __shfl_xor_sync(0xffffffffu, s1, 1);
        s1 += __shfl_xor_sync(0xffffffffu, s1, 2);
        if (t == 0){
            int rl = wm*32 + mf*16 + g;
            atomicAdd(&ls[rl],   s0);
            atomicAdd(&ls[rl+8], s1);
        }
    }
    __syncthreads();
    if (tid < 64) atomicAdd(&sums[m0 + tid], ls[tid]);
}

__global__ void k_pos(const float* __restrict__ GselU, const float* __restrict__ Eu,
                      const float* __restrict__ GselI, const float* __restrict__ Ei,
                      const int* __restrict__ uids, const int* __restrict__ iids,
                      float* scal){
    int w = (blockIdx.x*blockDim.x + threadIdx.x) >> 5;
    int lane = threadIdx.x & 31;
    if (w >= NUID + NIID) return;
    const float *g, *e; int slot;
    if (w < NUID){ int k = uids[w];      g = GselU + (size_t)w*DIMV;        e = Eu + (size_t)k*DIMV; slot=0; }
    else         { int wi = w - NUID; int k = iids[wi]; g = GselI + (size_t)wi*DIMV; e = Ei + (size_t)k*DIMV; slot=1; }
    float2 a = ((const float2*)g)[lane];
    float2 b = ((const float2*)e)[lane];
    float d = a.x*b.x + a.y*b.y;
    for (int off=16; off>0; off>>=1) d += __shfl_xor_sync(0xffffffffu, d, off);
    if (lane == 0){
        float v = fminf(fmaxf(d*5.0f, -5.0f), 5.0f);
        atomicAdd(&scal[slot], v);
    }
}

__global__ void k_out(const float* __restrict__ Eu, const float* __restrict__ Ei,
                      const float* __restrict__ iu, const float* __restrict__ tu,
                      const float* __restrict__ ii, const float* __restrict__ ti,
                      float* __restrict__ out){
    int row = blockIdx.x*8 + (threadIdx.x >> 5);
    int lane = threadIdx.x & 31;
    const float *e, *a, *b; float* o;
    if (row < NU){
        e = Eu + (size_t)row*DIMV; a = iu + (size_t)row*DIMV; b = tu + (size_t)row*DIMV;
        o = out + (size_t)row*DIMV;
    } else {
        int r = row - NU;
        e = Ei + (size_t)r*DIMV; a = ii + (size_t)r*DIMV; b = ti + (size_t)r*DIMV;
        o = out + (size_t)NU*DIMV + (size_t)r*DIMV;
    }
    float2 e2 = ((const float2*)e)[lane];
    float2 a2 = ((const float2*)a)[lane];
    float2 b2 = ((const float2*)b)[lane];
    float sa = a2.x*a2.x + a2.y*a2.y;
    float sb = b2.x*b2.x + b2.y*b2.y;
    for (int off=16; off>0; off>>=1){
        sa += __shfl_xor_sync(0xffffffffu, sa, off);
        sb += __shfl_xor_sync(0xffffffffu, sb, off);
    }
    float na = fmaxf(sqrtf(sa), 1e-12f);
    float nb = fmaxf(sqrtf(sb), 1e-12f);
    float2 r2;
    r2.x = e2.x + 0.02f*(a2.x/na) + 0.02f*(b2.x/nb);
    r2.y = e2.y + 0.02f*(a2.y/na) + 0.02f*(b2.y/nb);
    ((float2*)o)[lane] = r2;
}

__global__ void k_loss(const float* __restrict__ sumU, const float* __restrict__ sumI,
                       const float* __restrict__ scal, float* outp){
    __shared__ float sh[256];
    int tid = threadIdx.x;
    float acc = 0.f;
    for (int k=tid; k<NUID; k+=256) acc += logf(sumU[k]) * (1.0f/NUID);
    for (int k=tid; k<NIID; k+=256) acc += logf(sumI[k]) * (1.0f/NIID);
    sh[tid] = acc;
    __syncthreads();
    for (int off=128; off>0; off>>=1){
        if (tid < off) sh[tid] += sh[tid+off];
        __syncthreads();
    }
    if (tid == 0){
        float neg = sh[0];
        float pos = scal[0]*(1.0f/NUID) + scal[1]*(1.0f/NIID);
        outp[0] = (neg - pos) * 4.0f;   // * (len(G_u_list)+1)
    }
}

// ---------------- launcher ----------------
extern "C" void kernel_launch(void* const* d_in, const int* in_sizes, int n_in,
                              void* d_out, int out_size){
    const float* user_emb     = (const float*)d_in[0];
    const float* item_emb     = (const float*)d_in[1];
    const float* user_emb_pre = (const float*)d_in[2];
    const float* item_emb_pre = (const float*)d_in[3];
    const float* img_item     = (const float*)d_in[4];
    const float* txt_item     = (const float*)d_in[5];
    const float* img_user     = (const float*)d_in[6];
    const float* txt_user     = (const float*)d_in[7];
    const int*   arows        = (const int*)d_in[8];
    const int*   acols        = (const int*)d_in[9];
    const float* avals        = (const float*)d_in[10];
    const float* ut           = (const float*)d_in[11];
    const float* vt           = (const float*)d_in[12];
    const float* u_mul_s      = (const float*)d_in[13];
    const float* v_mul_s      = (const float*)d_in[14];
    const int*   uids         = (const int*)d_in[15];
    const int*   iids         = (const int*)d_in[16];
    float* out = (float*)d_out;

    float *Eu0,*Ei0,*Zu1,*Zi1,*Eu,*Ei,*GselU,*GselI,*P1,*P2,*sumU,*sumI,*scal,*rvals,*cvals;
    __nv_bfloat16 *EbfU,*EbfI,*AbfU,*AbfI;
    int *rcnt,*rbase,*rfill,*ccnt,*cbase,*cfill,*rcols,*crows,*bsU,*bsI;
    cudaGetSymbolAddress((void**)&Eu0,  g_Eu0);
    cudaGetSymbolAddress((void**)&Ei0,  g_Ei0);
    cudaGetSymbolAddress((void**)&Zu1,  g_Zu1);
    cudaGetSymbolAddress((void**)&Zi1,  g_Zi1);
    cudaGetSymbolAddress((void**)&Eu,   g_Eu);
    cudaGetSymbolAddress((void**)&Ei,   g_Ei);
    cudaGetSymbolAddress((void**)&EbfU, g_EbfU);
    cudaGetSymbolAddress((void**)&EbfI, g_EbfI);
    cudaGetSymbolAddress((void**)&GselU,g_GselU);
    cudaGetSymbolAddress((void**)&GselI,g_GselI);
    cudaGetSymbolAddress((void**)&AbfU, g_AbfU);
    cudaGetSymbolAddress((void**)&AbfI, g_AbfI);
    cudaGetSymbolAddress((void**)&P1,   g_P1);
    cudaGetSymbolAddress((void**)&P2,   g_P2);
    cudaGetSymbolAddress((void**)&sumU, g_sumU);
    cudaGetSymbolAddress((void**)&sumI, g_sumI);
    cudaGetSymbolAddress((void**)&scal, g_scal);
    cudaGetSymbolAddress((void**)&rcnt, g_rcnt);
    cudaGetSymbolAddress((void**)&rbase,g_rbase);
    cudaGetSymbolAddress((void**)&rfill,g_rfill);
    cudaGetSymbolAddress((void**)&ccnt, g_ccnt);
    cudaGetSymbolAddress((void**)&cbase,g_cbase);
    cudaGetSymbolAddress((void**)&cfill,g_cfill);
    cudaGetSymbolAddress((void**)&rcols,g_rcols);
    cudaGetSymbolAddress((void**)&rvals,g_rvals);
    cudaGetSymbolAddress((void**)&crows,g_crows);
    cudaGetSymbolAddress((void**)&cvals,g_cvals);
    cudaGetSymbolAddress((void**)&bsU,  g_bsU);
    cudaGetSymbolAddress((void**)&bsI,  g_bsI);

    // init + CSR/CSC build
    k_zero<<<(NU+255)/256, 256>>>(rcnt,rfill,ccnt,cfill,P1,P2,sumU,sumI,scal);
    k_init<<<((NU+NI)*16+255)/256, 256>>>((const float4*)user_emb,(const float4*)user_emb_pre,
                                          (const float4*)item_emb,(const float4*)item_emb_pre,
                                          (float4*)Eu0,(float4*)Ei0);
    k_count<<<(NNZE+255)/256, 256>>>(arows, acols, rcnt, ccnt);
    k_scan_block<<<98, 1024>>>(rcnt, NU, rbase, bsU);
    k_scan_top<<<1, 128>>>(bsU, 98);
    k_scan_add<<<98, 1024>>>(rbase, NU, bsU);
    k_scan_block<<<49, 1024>>>(ccnt, NI, cbase, bsI);
    k_scan_top<<<1, 128>>>(bsI, 49);
    k_scan_add<<<49, 1024>>>(cbase, NI, bsI);
    k_scatter<<<(NNZE+255)/256, 256>>>(arows,acols,avals, rbase,rfill,rcols,rvals,
                                       cbase,cfill,crows,cvals);

    // GNN layer 1
    k_spmm<<<NU/16, 256>>>(rbase,rcnt,rcols,rvals, Ei0, nullptr,nullptr, 1.0f, Zu1, nullptr, NU);
    k_spmm<<<NI/16, 256>>>(cbase,ccnt,crows,cvals, Eu0, nullptr,nullptr, 1.0f, Zi1, nullptr, NI);
    // GNN layer 2 fused with averaging: E = (E0 + Z1 + Z2)/3, also emit bf16
    k_spmm<<<NU/16, 256>>>(rbase,rcnt,rcols,rvals, Zi1, Eu0, Zu1, 1.0f/3.0f, Eu, EbfU, NU);
    k_spmm<<<NI/16, 256>>>(cbase,ccnt,crows,cvals, Zu1, Ei0, Zi1, 1.0f/3.0f, Ei, EbfI, NI);

    // low-rank SVD path (only gathered G rows are needed downstream)
    k_lowrank<<<128, 256>>>(vt, Ei0, Zi1, P1, NI);
    k_lowrank<<<128, 256>>>(ut, Eu0, Zu1, P2, NU);
    k_gsel<<<(NUID*DIMV)/256, 256>>>(uids, Eu0, u_mul_s, P1, GselU, AbfU, NUID);
    k_gsel<<<(NIID*DIMV)/256, 256>>>(iids, Ei0, v_mul_s, P2, GselI, AbfI, NIID);

    // contrastive loss: tensor-core logsumexp GEMM
    k_negmma<<<dim3((NU+127)/128, NUID/64), 256>>>(AbfU, EbfU, NU, sumU);
    k_negmma<<<dim3((NI+127)/128, NIID/64), 256>>>(AbfI, EbfI, NI, sumI);
    k_pos<<<(NUID+NIID)/8, 256>>>(GselU, Eu, GselI, Ei, uids, iids, scal);

    // outputs
    k_out<<<(NU+NI)/8, 256>>>(Eu, Ei, img_user, txt_user, img_item, txt_item, out);
    k_loss<<<1, 256>>>(sumU, sumI, scal, out + (size_t)(NU+NI)*DIMV);
}

// round 3
// speedup vs baseline: 2.9368x; 1.0658x over previous
#include <cuda_runtime.h>
#include <cuda_bf16.h>
#include <math.h>

#define NU 100000
#define NI 50000
#define DIMV 64
#define RK 5
#define NNZE 2000000
#define NUID 2048
#define NIID 4096

// ---------------- device scratch (no allocations allowed) ----------------
__device__ __align__(16) float g_Eu0[NU*DIMV];
__device__ __align__(16) float g_Ei0[NI*DIMV];
__device__ __align__(16) float g_Zu1[NU*DIMV];
__device__ __align__(16) float g_Zi1[NI*DIMV];
__device__ __align__(16) float g_Eu [NU*DIMV];
__device__ __align__(16) float g_Ei [NI*DIMV];
__device__ __align__(16) __nv_bfloat16 g_EbfU[NU*DIMV];
__device__ __align__(16) __nv_bfloat16 g_EbfI[NI*DIMV];
__device__ __align__(16) float g_GselU[NUID*DIMV];
__device__ __align__(16) float g_GselI[NIID*DIMV];
__device__ __align__(16) __nv_bfloat16 g_AbfU[NUID*DIMV];
__device__ __align__(16) __nv_bfloat16 g_AbfI[NIID*DIMV];
__device__ float g_P1[RK*DIMV];
__device__ float g_P2[RK*DIMV];
__device__ int   g_rcnt[NU];
__device__ int   g_rbase[NU];
__device__ int   g_rfill[NU];
__device__ int   g_ccnt[NI];
__device__ int   g_cbase[NI];
__device__ int   g_cfill[NI];
__device__ __align__(16) int2 g_redge[NNZE];   // (col, val_bits)
__device__ __align__(16) int2 g_cedge[NNZE];   // (row, val_bits)
__device__ int   g_bsU[128];
__device__ int   g_bsI[128];
__device__ float g_sumU[NUID];
__device__ float g_sumI[NIID];
__device__ float g_scal[8];

// ---------------- kernels ----------------

// fused zero + E0 init
__global__ void k_setup(const float4* __restrict__ ue, const float4* __restrict__ uep,
                        const float4* __restrict__ ie, const float4* __restrict__ iep,
                        float4* __restrict__ Eu0, float4* __restrict__ Ei0,
                        int* rcnt,int* rfill,int* ccnt,int* cfill,
                        float* P1,float* P2,float* sumU,float* sumI,float* scal){
    int i = blockIdx.x*256 + threadIdx.x;
    if (i < NU*16){
        float4 a = ue[i], b = uep[i];
        Eu0[i] = make_float4(a.x+b.x, a.y+b.y, a.z+b.z, a.w+b.w);
    } else if (i < (NU+NI)*16){
        int k = i - NU*16;
        float4 a = ie[k], b = iep[k];
        Ei0[k] = make_float4(a.x+b.x, a.y+b.y, a.z+b.z, a.w+b.w);
    }
    if (i < NU){ rcnt[i]=0; rfill[i]=0; }
    if (i < NI){ ccnt[i]=0; cfill[i]=0; }
    if (i < NUID) sumU[i]=0.f;
    if (i < NIID) sumI[i]=0.f;
    if (i < RK*DIMV){ P1[i]=0.f; P2[i]=0.f; }
    if (i < 8) scal[i]=0.f;
}

__global__ void k_count(const int* __restrict__ rows, const int* __restrict__ cols,
                        int* rcnt, int* ccnt){
    int e = blockIdx.x*256 + threadIdx.x;
    if (e < NNZE){
        atomicAdd(&rcnt[rows[e]], 1);
        atomicAdd(&ccnt[cols[e]], 1);
    }
}

__global__ void k_scan_block(const int* __restrict__ cnt, int n, int* base, int* bsums){
    __shared__ int sh[1024];
    int i = blockIdx.x*1024 + threadIdx.x;
    int v = (i < n) ? cnt[i] : 0;
    sh[threadIdx.x] = v;
    __syncthreads();
    for (int off=1; off<1024; off<<=1){
        int t = (threadIdx.x >= off) ? sh[threadIdx.x-off] : 0;
        __syncthreads();
        sh[threadIdx.x] += t;
        __syncthreads();
    }
    if (i < n) base[i] = sh[threadIdx.x] - v;
    if (threadIdx.x == 1023) bsums[blockIdx.x] = sh[1023];
}

__global__ void k_scan_top(int* bsums, int nb){
    __shared__ int sh[128];
    int tid = threadIdx.x;
    int v = (tid < nb) ? bsums[tid] : 0;
    sh[tid] = v;
    __syncthreads();
    for (int off=1; off<128; off<<=1){
        int t = (tid >= off) ? sh[tid-off] : 0;
        __syncthreads();
        sh[tid] += t;
        __syncthreads();
    }
    if (tid < nb) bsums[tid] = sh[tid] - v;
}

__global__ void k_scan_add(int* base, int n, const int* __restrict__ bsums){
    int i = blockIdx.x*1024 + threadIdx.x;
    if (i < n) base[i] += bsums[i >> 10];
}

__global__ void k_scatter(const int* __restrict__ rows, const int* __restrict__ cols,
                          const float* __restrict__ vals,
                          const int* __restrict__ rbase, int* rfill, int2* redge,
                          const int* __restrict__ cbase, int* cfill, int2* cedge){
    int e = blockIdx.x*256 + threadIdx.x;
    if (e < NNZE){
        int r = rows[e], c = cols[e];
        int vb = __float_as_int(vals[e]);
        int pr = rbase[r] + atomicAdd(&rfill[r], 1);
        redge[pr] = make_int2(c, vb);
        int pc = cbase[c] + atomicAdd(&cfill[c], 1);
        cedge[pc] = make_int2(r, vb);
    }
}

// gather-style SpMM: dst[row] = (sum_e v*src[nbr] + add0[row] + add1[row]) * scale
// unroll-4 for memory-level parallelism; optionally emits bf16 copy
__global__ void k_spmm(const int* __restrict__ base, const int* __restrict__ cnt,
                       const int2* __restrict__ edges,
                       const float* __restrict__ src,
                       const float* __restrict__ add0, const float* __restrict__ add1,
                       float scale, float* __restrict__ dst,
                       __nv_bfloat16* __restrict__ bdst, int nrows){
    int row = blockIdx.x*16 + (threadIdx.x >> 4);
    int lane = threadIdx.x & 15;
    if (row >= nrows) return;
    int s = base[row], n = cnt[row];
    float4 acc = make_float4(0.f,0.f,0.f,0.f);
    const float4* src4 = (const float4*)src;
    int p = 0;
    for (; p + 4 <= n; p += 4){
        int2 e0 = edges[s+p+0], e1 = edges[s+p+1], e2 = edges[s+p+2], e3 = edges[s+p+3];
        float4 x0 = src4[(size_t)e0.x*16 + lane];
        float4 x1 = src4[(size_t)e1.x*16 + lane];
        float4 x2 = src4[(size_t)e2.x*16 + lane];
        float4 x3 = src4[(size_t)e3.x*16 + lane];
        float v0 = __int_as_float(e0.y), v1 = __int_as_float(e1.y);
        float v2 = __int_as_float(e2.y), v3 = __int_as_float(e3.y);
        acc.x = fmaf(v0,x0.x, fmaf(v1,x1.x, fmaf(v2,x2.x, fmaf(v3,x3.x, acc.x))));
        acc.y = fmaf(v0,x0.y, fmaf(v1,x1.y, fmaf(v2,x2.y, fmaf(v3,x3.y, acc.y))));
        acc.z = fmaf(v0,x0.z, fmaf(v1,x1.z, fmaf(v2,x2.z, fmaf(v3,x3.z, acc.z))));
        acc.w = fmaf(v0,x0.w, fmaf(v1,x1.w, fmaf(v2,x2.w, fmaf(v3,x3.w, acc.w))));
    }
    for (; p < n; p++){
        int2 e = edges[s+p];
        float v = __int_as_float(e.y);
        float4 x = src4[(size_t)e.x*16 + lane];
        acc.x = fmaf(v, x.x, acc.x);
        acc.y = fmaf(v, x.y, acc.y);
        acc.z = fmaf(v, x.z, acc.z);
        acc.w = fmaf(v, x.w, acc.w);
    }
    size_t o = (size_t)row*16 + lane;
    if (add0){ float4 a = ((const float4*)add0)[o]; acc.x+=a.x; acc.y+=a.y; acc.z+=a.z; acc.w+=a.w; }
    if (add1){ float4 a = ((const float4*)add1)[o]; acc.x+=a.x; acc.y+=a.y; acc.z+=a.z; acc.w+=a.w; }
    acc.x*=scale; acc.y*=scale; acc.z*=scale; acc.w*=scale;
    ((float4*)dst)[o] = acc;
    if (bdst){
        __nv_bfloat162 b0 = __floats2bfloat162_rn(acc.x, acc.y);
        __nv_bfloat162 b1 = __floats2bfloat162_rn(acc.z, acc.w);
        ((__nv_bfloat162*)bdst)[o*2+0] = b0;
        ((__nv_bfloat162*)bdst)[o*2+1] = b1;
    }
}

// P[r][d] += sum_i fac[r*n+i] * (A[i][d] + B[i][d])
__global__ void k_lowrank(const float* __restrict__ fac, const float* __restrict__ A,
                          const float* __restrict__ B, float* __restrict__ P, int n){
    int d  = threadIdx.x & 63;
    int il = threadIdx.x >> 6;   // 0..3
    int chunk = (n + gridDim.x - 1) / gridDim.x;
    int i0 = blockIdx.x*chunk;
    int i1 = min(i0 + chunk, n);
    float acc[RK];
    #pragma unroll
    for (int r=0;r<RK;r++) acc[r]=0.f;
    for (int i=i0+il; i<i1; i+=4){
        float m = A[(size_t)i*DIMV + d] + B[(size_t)i*DIMV + d];
        #pragma unroll
        for (int r=0;r<RK;r++) acc[r] = fmaf(fac[(size_t)r*n + i], m, acc[r]);
    }
    __shared__ float red[4][RK][DIMV];
    #pragma unroll
    for (int r=0;r<RK;r++) red[il][r][d] = acc[r];
    __syncthreads();
    if (il == 0){
        #pragma unroll
        for (int r=0;r<RK;r++){
            float t = red[0][r][d] + red[1][r][d] + red[2][r][d] + red[3][r][d];
            atomicAdd(&P[r*DIMV + d], t);
        }
    }
}

// gathered G rows only: Gsel[w] = (E0[id] + muls[id] @ P)/3 ; Abf = bf16(Gsel * 5*log2e)
__global__ void k_gsel(const int* __restrict__ ids, const float* __restrict__ base0,
                       const float* __restrict__ muls, const float* __restrict__ P,
                       float* __restrict__ Gsel, __nv_bfloat16* __restrict__ Abf, int nids){
    int i = blockIdx.x*256 + threadIdx.x;
    if (i >= nids*DIMV) return;
    int w = i >> 6, d = i & 63;
    int id = ids[w];
    float s = base0[(size_t)id*DIMV + d];
    #pragma unroll
    for (int r=0;r<RK;r++) s = fmaf(muls[(size_t)id*RK + r], P[r*DIMV + d], s);
    s *= (1.0f/3.0f);
    Gsel[i] = s;
    Abf[i] = __float2bfloat16(s * 7.2134752044448170f);  // (1/T) * log2(e)
}

__device__ __forceinline__ float ex2f(float x){
    float r;
    asm("ex2.approx.f32 %0, %1;" : "=f"(r) : "f"(x));
    return r;
}

// sums[m0+r] += sum_j exp2( dot(Abf[m0+r], Ebf[j]) )   (scale pre-folded into A)
// CTA tile: 128 ids x 128 cols, K=64 single shot. 8 warps = 4(M) x 2(N), warp 32x64.
__global__ void __launch_bounds__(256,2) k_negmma(
        const __nv_bfloat16* __restrict__ A, const __nv_bfloat16* __restrict__ E,
        int NJ, float* __restrict__ sums){
    __shared__ __nv_bfloat16 As[128][72];
    __shared__ __nv_bfloat16 Bs[128][72];
    __shared__ float ls[128];
    int tid = threadIdx.x;
    int m0 = blockIdx.y * 128;
    int jbase = blockIdx.x * 128;
    if (tid < 128) ls[tid] = 0.f;

    #pragma unroll
    for (int c = tid; c < 1024; c += 256){
        int r = c >> 3, c8 = c & 7;
        *(uint4*)&As[r][c8*8] = *(const uint4*)(A + (size_t)(m0 + r)*DIMV + c8*8);
        int j = jbase + r;
        uint4 v = make_uint4(0u,0u,0u,0u);
        if (j < NJ) v = *(const uint4*)(E + (size_t)j*DIMV + c8*8);
        *(uint4*)&Bs[r][c8*8] = v;
    }
    __syncthreads();

    int warp = tid >> 5, lane = tid & 31;
    int wm = warp >> 1, wn = warp & 1;
    int g = lane >> 2, t = lane & 3;

    float acc[2][8][4];
    #pragma unroll
    for (int mf=0;mf<2;mf++)
        #pragma unroll
        for (int nf=0;nf<8;nf++)
            #pragma unroll
            for (int q=0;q<4;q++) acc[mf][nf][q]=0.f;

    #pragma unroll
    for (int kk=0; kk<4; kk++){
        int kb = kk*16 + 2*t;
        unsigned a[2][4], b[8][2];
        #pragma unroll
        for (int mf=0; mf<2; mf++){
            int r = wm*32 + mf*16 + g;
            a[mf][0] = *(const unsigned*)&As[r  ][kb  ];
            a[mf][1] = *(const unsigned*)&As[r+8][kb  ];
            a[mf][2] = *(const unsigned*)&As[r  ][kb+8];
            a[mf][3] = *(const unsigned*)&As[r+8][kb+8];
        }
        #pragma unroll
        for (int nf=0; nf<8; nf++){
            int n = wn*64 + nf*8 + g;
            b[nf][0] = *(const unsigned*)&Bs[n][kb  ];
            b[nf][1] = *(const unsigned*)&Bs[n][kb+8];
        }
        #pragma unroll
        for (int mf=0; mf<2; mf++)
            #pragma unroll
            for (int nf=0; nf<8; nf++)
                asm volatile(
                    "mma.sync.aligned.m16n8k16.row.col.f32.bf16.bf16.f32 "
                    "{%0,%1,%2,%3}, {%4,%5,%6,%7}, {%8,%9}, {%0,%1,%2,%3};"
                    : "+f"(acc[mf][nf][0]), "+f"(acc[mf][nf][1]),
                      "+f"(acc[mf][nf][2]), "+f"(acc[mf][nf][3])
                    : "r"(a[mf][0]), "r"(a[mf][1]), "r"(a[mf][2]), "r"(a[mf][3]),
                      "r"(b[nf][0]), "r"(b[nf][1]));
    }

    // epilogue: exp2 + masked sum per row
    #pragma unroll
    for (int mf=0; mf<2; mf++){
        float s0 = 0.f, s1 = 0.f;
        #pragma unroll
        for (int nf=0; nf<8; nf++){
            int jc = jbase + wn*64 + nf*8 + 2*t;
            bool v0 = jc < NJ, v1 = (jc+1) < NJ;
            s0 += (v0 ? ex2f(acc[mf][nf][0]) : 0.f) + (v1 ? ex2f(acc[mf][nf][1]) : 0.f);
            s1 += (v0 ? ex2f(acc[mf][nf][2]) : 0.f) + (v1 ? ex2f(acc[mf][nf][3]) : 0.f);
        }
        s0 += __shfl_xor_sync(0xffffffffu, s0, 1);
        s0 += __shfl_xor_sync(0xffffffffu, s0, 2);
        s1 += __shfl_xor_sync(0xffffffffu, s1, 1);
        s1 += __shfl_xor_sync(0xffffffffu, s1, 2);
        if (t == 0){
            int rl = wm*32 + mf*16 + g;
            atomicAdd(&ls[rl],   s0);
            atomicAdd(&ls[rl+8], s1);
        }
    }
    __syncthreads();
    if (tid < 128) atomicAdd(&sums[m0 + tid], ls[tid]);
}

__global__ void k_pos(const float* __restrict__ GselU, const float* __restrict__ Eu,
                      const float* __restrict__ GselI, const float* __restrict__ Ei,
                      const int* __restrict__ uids, const int* __restrict__ iids,
                      float* scal){
    int w = (blockIdx.x*blockDim.x + threadIdx.x) >> 5;
    int lane = threadIdx.x & 31;
    if (w >= NUID + NIID) return;
    const float *g, *e; int slot;
    if (w < NUID){ int k = uids[w];      g = GselU + (size_t)w*DIMV;        e = Eu + (size_t)k*DIMV; slot=0; }
    else         { int wi = w - NUID; int k = iids[wi]; g = GselI + (size_t)wi*DIMV; e = Ei + (size_t)k*DIMV; slot=1; }
    float2 a = ((const float2*)g)[lane];
    float2 b = ((const float2*)e)[lane];
    float d = a.x*b.x + a.y*b.y;
    for (int off=16; off>0; off>>=1) d += __shfl_xor_sync(0xffffffffu, d, off);
    if (lane == 0){
        float v = fminf(fmaxf(d*5.0f, -5.0f), 5.0f);
        atomicAdd(&scal[slot], v);
    }
}

__global__ void k_out(const float* __restrict__ Eu, const float* __restrict__ Ei,
                      const float* __restrict__ iu, const float* __restrict__ tu,
                      const float* __restrict__ ii, const float* __restrict__ ti,
                      float* __restrict__ out){
    int row = blockIdx.x*8 + (threadIdx.x >> 5);
    int lane = threadIdx.x & 31;
    const float *e, *a, *b; float* o;
    if (row < NU){
        e = Eu + (size_t)row*DIMV; a = iu + (size_t)row*DIMV; b = tu + (size_t)row*DIMV;
        o = out + (size_t)row*DIMV;
    } else {
        int r = row - NU;
        e = Ei + (size_t)r*DIMV; a = ii + (size_t)r*DIMV; b = ti + (size_t)r*DIMV;
        o = out + (size_t)NU*DIMV + (size_t)r*DIMV;
    }
    float2 e2 = ((const float2*)e)[lane];
    float2 a2 = ((const float2*)a)[lane];
    float2 b2 = ((const float2*)b)[lane];
    float sa = a2.x*a2.x + a2.y*a2.y;
    float sb = b2.x*b2.x + b2.y*b2.y;
    for (int off=16; off>0; off>>=1){
        sa += __shfl_xor_sync(0xffffffffu, sa, off);
        sb += __shfl_xor_sync(0xffffffffu, sb, off);
    }
    float na = fmaxf(sqrtf(sa), 1e-12f);
    float nb = fmaxf(sqrtf(sb), 1e-12f);
    float2 r2;
    r2.x = e2.x + 0.02f*(a2.x/na) + 0.02f*(b2.x/nb);
    r2.y = e2.y + 0.02f*(a2.y/na) + 0.02f*(b2.y/nb);
    ((float2*)o)[lane] = r2;
}

__global__ void k_loss(const float* __restrict__ sumU, const float* __restrict__ sumI,
                       const float* __restrict__ scal, float* outp){
    __shared__ float sh[256];
    int tid = threadIdx.x;
    float acc = 0.f;
    for (int k=tid; k<NUID; k+=256) acc += logf(sumU[k]) * (1.0f/NUID);
    for (int k=tid; k<NIID; k+=256) acc += logf(sumI[k]) * (1.0f/NIID);
    sh[tid] = acc;
    __syncthreads();
    for (int off=128; off>0; off>>=1){
        if (tid < off) sh[tid] += sh[tid+off];
        __syncthreads();
    }
    if (tid == 0){
        float neg = sh[0];
        float pos = scal[0]*(1.0f/NUID) + scal[1]*(1.0f/NIID);
        outp[0] = (neg - pos) * 4.0f;   // * (len(G_u_list)+1)
    }
}

// ---------------- launcher ----------------
extern "C" void kernel_launch(void* const* d_in, const int* in_sizes, int n_in,
                              void* d_out, int out_size){
    const float* user_emb     = (const float*)d_in[0];
    const float* item_emb     = (const float*)d_in[1];
    const float* user_emb_pre = (const float*)d_in[2];
    const float* item_emb_pre = (const float*)d_in[3];
    const float* img_item     = (const float*)d_in[4];
    const float* txt_item     = (const float*)d_in[5];
    const float* img_user     = (const float*)d_in[6];
    const float* txt_user     = (const float*)d_in[7];
    const int*   arows        = (const int*)d_in[8];
    const int*   acols        = (const int*)d_in[9];
    const float* avals        = (const float*)d_in[10];
    const float* ut           = (const float*)d_in[11];
    const float* vt           = (const float*)d_in[12];
    const float* u_mul_s      = (const float*)d_in[13];
    const float* v_mul_s      = (const float*)d_in[14];
    const int*   uids         = (const int*)d_in[15];
    const int*   iids         = (const int*)d_in[16];
    float* out = (float*)d_out;

    float *Eu0,*Ei0,*Zu1,*Zi1,*Eu,*Ei,*GselU,*GselI,*P1,*P2,*sumU,*sumI,*scal;
    __nv_bfloat16 *EbfU,*EbfI,*AbfU,*AbfI;
    int *rcnt,*rbase,*rfill,*ccnt,*cbase,*cfill,*bsU,*bsI;
    int2 *redge,*cedge;
    cudaGetSymbolAddress((void**)&Eu0,  g_Eu0);
    cudaGetSymbolAddress((void**)&Ei0,  g_Ei0);
    cudaGetSymbolAddress((void**)&Zu1,  g_Zu1);
    cudaGetSymbolAddress((void**)&Zi1,  g_Zi1);
    cudaGetSymbolAddress((void**)&Eu,   g_Eu);
    cudaGetSymbolAddress((void**)&Ei,   g_Ei);
    cudaGetSymbolAddress((void**)&EbfU, g_EbfU);
    cudaGetSymbolAddress((void**)&EbfI, g_EbfI);
    cudaGetSymbolAddress((void**)&GselU,g_GselU);
    cudaGetSymbolAddress((void**)&GselI,g_GselI);
    cudaGetSymbolAddress((void**)&AbfU, g_AbfU);
    cudaGetSymbolAddress((void**)&AbfI, g_AbfI);
    cudaGetSymbolAddress((void**)&P1,   g_P1);
    cudaGetSymbolAddress((void**)&P2,   g_P2);
    cudaGetSymbolAddress((void**)&sumU, g_sumU);
    cudaGetSymbolAddress((void**)&sumI, g_sumI);
    cudaGetSymbolAddress((void**)&scal, g_scal);
    cudaGetSymbolAddress((void**)&rcnt, g_rcnt);
    cudaGetSymbolAddress((void**)&rbase,g_rbase);
    cudaGetSymbolAddress((void**)&rfill,g_rfill);
    cudaGetSymbolAddress((void**)&ccnt, g_ccnt);
    cudaGetSymbolAddress((void**)&cbase,g_cbase);
    cudaGetSymbolAddress((void**)&cfill,g_cfill);
    cudaGetSymbolAddress((void**)&redge,g_redge);
    cudaGetSymbolAddress((void**)&cedge,g_cedge);
    cudaGetSymbolAddress((void**)&bsU,  g_bsU);
    cudaGetSymbolAddress((void**)&bsI,  g_bsI);

    // init + CSR/CSC build
    k_setup<<<((NU+NI)*16+255)/256, 256>>>((const float4*)user_emb,(const float4*)user_emb_pre,
                                           (const float4*)item_emb,(const float4*)item_emb_pre,
                                           (float4*)Eu0,(float4*)Ei0,
                                           rcnt,rfill,ccnt,cfill,P1,P2,sumU,sumI,scal);
    k_count<<<(NNZE+255)/256, 256>>>(arows, acols, rcnt, ccnt);
    k_scan_block<<<98, 1024>>>(rcnt, NU, rbase, bsU);
    k_scan_top<<<1, 128>>>(bsU, 98);
    k_scan_add<<<98, 1024>>>(rbase, NU, bsU);
    k_scan_block<<<49, 1024>>>(ccnt, NI, cbase, bsI);
    k_scan_top<<<1, 128>>>(bsI, 49);
    k_scan_add<<<49, 1024>>>(cbase, NI, bsI);
    k_scatter<<<(NNZE+255)/256, 256>>>(arows,acols,avals, rbase,rfill,redge,
                                       cbase,cfill,cedge);

    // GNN layer 1
    k_spmm<<<NU/16, 256>>>(rbase,rcnt,redge, Ei0, nullptr,nullptr, 1.0f, Zu1, nullptr, NU);
    k_spmm<<<NI/16, 256>>>(cbase,ccnt,cedge, Eu0, nullptr,nullptr, 1.0f, Zi1, nullptr, NI);
    // GNN layer 2 fused with averaging: E = (E0 + Z1 + Z2)/3, also emit bf16
    k_spmm<<<NU/16, 256>>>(rbase,rcnt,redge, Zi1, Eu0, Zu1, 1.0f/3.0f, Eu, EbfU, NU);
    k_spmm<<<NI/16, 256>>>(cbase,ccnt,cedge, Zu1, Ei0, Zi1, 1.0f/3.0f, Ei, EbfI, NI);

    // low-rank SVD path (only gathered G rows are needed downstream)
    k_lowrank<<<128, 256>>>(vt, Ei0, Zi1, P1, NI);
    k_lowrank<<<128, 256>>>(ut, Eu0, Zu1, P2, NU);
    k_gsel<<<(NUID*DIMV)/256, 256>>>(uids, Eu0, u_mul_s, P1, GselU, AbfU, NUID);
    k_gsel<<<(NIID*DIMV)/256, 256>>>(iids, Ei0, v_mul_s, P2, GselI, AbfI, NIID);

    // contrastive loss: tensor-core logsumexp GEMM
    k_negmma<<<dim3((NU+127)/128, NUID/128), 256>>>(AbfU, EbfU, NU, sumU);
    k_negmma<<<dim3((NI+127)/128, NIID/128), 256>>>(AbfI, EbfI, NI, sumI);
    k_pos<<<(NUID+NIID)/8, 256>>>(GselU, Eu, GselI, Ei, uids, iids, scal);

    // outputs
    k_out<<<(NU+NI)/8, 256>>>(Eu, Ei, img_user, txt_user, img_item, txt_item, out);
    k_loss<<<1, 256>>>(sumU, sumI, scal, out + (size_t)(NU+NI)*DIMV);
}

// round 4
// speedup vs baseline: 3.0068x; 1.0238x over previous
#include <cuda_runtime.h>
#include <cuda_bf16.h>
#include <math.h>

#define NU 100000
#define NI 50000
#define DIMV 64
#define RK 5
#define NNZE 2000000
#define NUID 2048
#define NIID 4096

// ---------------- device scratch (no allocations allowed) ----------------
__device__ __align__(16) float g_Eu0[NU*DIMV];
__device__ __align__(16) float g_Ei0[NI*DIMV];
__device__ __align__(16) float g_Zu1[NU*DIMV];
__device__ __align__(16) float g_Zi1[NI*DIMV];
__device__ __align__(16) float g_Eu [NU*DIMV];
__device__ __align__(16) float g_Ei [NI*DIMV];
__device__ __align__(16) __nv_bfloat16 g_E0bfU[NU*DIMV];
__device__ __align__(16) __nv_bfloat16 g_E0bfI[NI*DIMV];
__device__ __align__(16) __nv_bfloat16 g_Z1bfU[NU*DIMV];
__device__ __align__(16) __nv_bfloat16 g_Z1bfI[NI*DIMV];
__device__ __align__(16) __nv_bfloat16 g_EbfU[NU*DIMV];
__device__ __align__(16) __nv_bfloat16 g_EbfI[NI*DIMV];
__device__ __align__(16) float g_GselU[NUID*DIMV];
__device__ __align__(16) float g_GselI[NIID*DIMV];
__device__ __align__(16) __nv_bfloat16 g_AbfU[NUID*DIMV];
__device__ __align__(16) __nv_bfloat16 g_AbfI[NIID*DIMV];
__device__ float g_P1[RK*DIMV];
__device__ float g_P2[RK*DIMV];
__device__ int   g_rcnt[NU];
__device__ int   g_rbase[NU];
__device__ int   g_rfill[NU];
__device__ int   g_ccnt[NI];
__device__ int   g_cbase[NI];
__device__ int   g_cfill[NI];
__device__ __align__(16) int2 g_redge[NNZE];   // (col, val_bits)
__device__ __align__(16) int2 g_cedge[NNZE];   // (row, val_bits)
__device__ int   g_bsU[128];
__device__ int   g_bsI[128];
__device__ float g_sumU[NUID];
__device__ float g_sumI[NIID];
__device__ float g_scal[8];

__device__ __forceinline__ uint2 pack_bf4(float4 v){
    __nv_bfloat162 p0 = __floats2bfloat162_rn(v.x, v.y);
    __nv_bfloat162 p1 = __floats2bfloat162_rn(v.z, v.w);
    uint2 r;
    r.x = *(unsigned*)&p0;
    r.y = *(unsigned*)&p1;
    return r;
}

// ---------------- kernels ----------------

// fused zero + E0 init (fp32 + bf16 copies)
__global__ void k_setup(const float4* __restrict__ ue, const float4* __restrict__ uep,
                        const float4* __restrict__ ie, const float4* __restrict__ iep,
                        float4* __restrict__ Eu0, float4* __restrict__ Ei0,
                        uint2* __restrict__ E0bfU, uint2* __restrict__ E0bfI,
                        int* rcnt,int* rfill,int* ccnt,int* cfill,
                        float* P1,float* P2,float* sumU,float* sumI,float* scal){
    int i = blockIdx.x*256 + threadIdx.x;
    if (i < NU*16){
        float4 a = ue[i], b = uep[i];
        float4 s = make_float4(a.x+b.x, a.y+b.y, a.z+b.z, a.w+b.w);
        Eu0[i] = s;
        E0bfU[i] = pack_bf4(s);
    } else if (i < (NU+NI)*16){
        int k = i - NU*16;
        float4 a = ie[k], b = iep[k];
        float4 s = make_float4(a.x+b.x, a.y+b.y, a.z+b.z, a.w+b.w);
        Ei0[k] = s;
        E0bfI[k] = pack_bf4(s);
    }
    if (i < NU){ rcnt[i]=0; rfill[i]=0; }
    if (i < NI){ ccnt[i]=0; cfill[i]=0; }
    if (i < NUID) sumU[i]=0.f;
    if (i < NIID) sumI[i]=0.f;
    if (i < RK*DIMV){ P1[i]=0.f; P2[i]=0.f; }
    if (i < 8) scal[i]=0.f;
}

__global__ void k_count(const int* __restrict__ rows, const int* __restrict__ cols,
                        int* rcnt, int* ccnt){
    int e = blockIdx.x*256 + threadIdx.x;
    if (e < NNZE){
        atomicAdd(&rcnt[rows[e]], 1);
        atomicAdd(&ccnt[cols[e]], 1);
    }
}

__global__ void k_scan_block(const int* __restrict__ cnt, int n, int* base, int* bsums){
    __shared__ int sh[1024];
    int i = blockIdx.x*1024 + threadIdx.x;
    int v = (i < n) ? cnt[i] : 0;
    sh[threadIdx.x] = v;
    __syncthreads();
    for (int off=1; off<1024; off<<=1){
        int t = (threadIdx.x >= off) ? sh[threadIdx.x-off] : 0;
        __syncthreads();
        sh[threadIdx.x] += t;
        __syncthreads();
    }
    if (i < n) base[i] = sh[threadIdx.x] - v;
    if (threadIdx.x == 1023) bsums[blockIdx.x] = sh[1023];
}

__global__ void k_scan_top(int* bsums, int nb){
    __shared__ int sh[128];
    int tid = threadIdx.x;
    int v = (tid < nb) ? bsums[tid] : 0;
    sh[tid] = v;
    __syncthreads();
    for (int off=1; off<128; off<<=1){
        int t = (tid >= off) ? sh[tid-off] : 0;
        __syncthreads();
        sh[tid] += t;
        __syncthreads();
    }
    if (tid < nb) bsums[tid] = sh[tid] - v;
}

__global__ void k_scan_add(int* base, int n, const int* __restrict__ bsums){
    int i = blockIdx.x*1024 + threadIdx.x;
    if (i < n) base[i] += bsums[i >> 10];
}

__global__ void k_scatter(const int* __restrict__ rows, const int* __restrict__ cols,
                          const float* __restrict__ vals,
                          const int* __restrict__ rbase, int* rfill, int2* redge,
                          const int* __restrict__ cbase, int* cfill, int2* cedge){
    int e = blockIdx.x*256 + threadIdx.x;
    if (e < NNZE){
        int r = rows[e], c = cols[e];
        int vb = __float_as_int(vals[e]);
        int pr = rbase[r] + atomicAdd(&rfill[r], 1);
        redge[pr] = make_int2(c, vb);
        int pc = cbase[c] + atomicAdd(&cfill[c], 1);
        cedge[pc] = make_int2(r, vb);
    }
}

// gather-style SpMM with bf16 source rows (fp32 accumulation):
// dst[row] = (sum_e v*srcbf[nbr] + add0[row] + add1[row]) * scale
__global__ void k_spmm(const int* __restrict__ base, const int* __restrict__ cnt,
                       const int2* __restrict__ edges,
                       const __nv_bfloat16* __restrict__ srcbf,
                       const float* __restrict__ add0, const float* __restrict__ add1,
                       float scale, float* __restrict__ dst,
                       __nv_bfloat16* __restrict__ bdst, int nrows){
    int row = blockIdx.x*16 + (threadIdx.x >> 4);
    int lane = threadIdx.x & 15;
    if (row >= nrows) return;
    int s = base[row], n = cnt[row];
    float4 acc = make_float4(0.f,0.f,0.f,0.f);
    const uint2* s2 = (const uint2*)srcbf;    // 16 uint2 per 64-elem bf16 row
    int p = 0;
    for (; p + 4 <= n; p += 4){
        int2 e0 = edges[s+p+0], e1 = edges[s+p+1], e2 = edges[s+p+2], e3 = edges[s+p+3];
        uint2 q0 = s2[(size_t)e0.x*16 + lane];
        uint2 q1 = s2[(size_t)e1.x*16 + lane];
        uint2 q2 = s2[(size_t)e2.x*16 + lane];
        uint2 q3 = s2[(size_t)e3.x*16 + lane];
        float v0 = __int_as_float(e0.y), v1 = __int_as_float(e1.y);
        float v2 = __int_as_float(e2.y), v3 = __int_as_float(e3.y);
        float2 a0 = __bfloat1622float2(*(const __nv_bfloat162*)&q0.x);
        float2 b0 = __bfloat1622float2(*(const __nv_bfloat162*)&q0.y);
        float2 a1 = __bfloat1622float2(*(const __nv_bfloat162*)&q1.x);
        float2 b1 = __bfloat1622float2(*(const __nv_bfloat162*)&q1.y);
        float2 a2 = __bfloat1622float2(*(const __nv_bfloat162*)&q2.x);
        float2 b2 = __bfloat1622float2(*(const __nv_bfloat162*)&q2.y);
        float2 a3 = __bfloat1622float2(*(const __nv_bfloat162*)&q3.x);
        float2 b3 = __bfloat1622float2(*(const __nv_bfloat162*)&q3.y);
        acc.x = fmaf(v0,a0.x, fmaf(v1,a1.x, fmaf(v2,a2.x, fmaf(v3,a3.x, acc.x))));
        acc.y = fmaf(v0,a0.y, fmaf(v1,a1.y, fmaf(v2,a2.y, fmaf(v3,a3.y, acc.y))));
        acc.z = fmaf(v0,b0.x, fmaf(v1,b1.x, fmaf(v2,b2.x, fmaf(v3,b3.x, acc.z))));
        acc.w = fmaf(v0,b0.y, fmaf(v1,b1.y, fmaf(v2,b2.y, fmaf(v3,b3.y, acc.w))));
    }
    for (; p < n; p++){
        int2 e = edges[s+p];
        float v = __int_as_float(e.y);
        uint2 q = s2[(size_t)e.x*16 + lane];
        float2 a = __bfloat1622float2(*(const __nv_bfloat162*)&q.x);
        float2 b = __bfloat1622float2(*(const __nv_bfloat162*)&q.y);
        acc.x = fmaf(v, a.x, acc.x);
        acc.y = fmaf(v, a.y, acc.y);
        acc.z = fmaf(v, b.x, acc.z);
        acc.w = fmaf(v, b.y, acc.w);
    }
    size_t o = (size_t)row*16 + lane;
    if (add0){ float4 a = ((const float4*)add0)[o]; acc.x+=a.x; acc.y+=a.y; acc.z+=a.z; acc.w+=a.w; }
    if (add1){ float4 a = ((const float4*)add1)[o]; acc.x+=a.x; acc.y+=a.y; acc.z+=a.z; acc.w+=a.w; }
    acc.x*=scale; acc.y*=scale; acc.z*=scale; acc.w*=scale;
    ((float4*)dst)[o] = acc;
    if (bdst) ((uint2*)bdst)[o] = pack_bf4(acc);
}

// P[r][d] += sum_i fac[r*n+i] * (A[i][d] + B[i][d])
__global__ void k_lowrank(const float* __restrict__ fac, const float* __restrict__ A,
                          const float* __restrict__ B, float* __restrict__ P, int n){
    int d  = threadIdx.x & 63;
    int il = threadIdx.x >> 6;   // 0..3
    int chunk = (n + gridDim.x - 1) / gridDim.x;
    int i0 = blockIdx.x*chunk;
    int i1 = min(i0 + chunk, n);
    float acc[RK];
    #pragma unroll
    for (int r=0;r<RK;r++) acc[r]=0.f;
    for (int i=i0+il; i<i1; i+=4){
        float m = A[(size_t)i*DIMV + d] + B[(size_t)i*DIMV + d];
        #pragma unroll
        for (int r=0;r<RK;r++) acc[r] = fmaf(fac[(size_t)r*n + i], m, acc[r]);
    }
    __shared__ float red[4][RK][DIMV];
    #pragma unroll
    for (int r=0;r<RK;r++) red[il][r][d] = acc[r];
    __syncthreads();
    if (il == 0){
        #pragma unroll
        for (int r=0;r<RK;r++){
            float t = red[0][r][d] + red[1][r][d] + red[2][r][d] + red[3][r][d];
            atomicAdd(&P[r*DIMV + d], t);
        }
    }
}

// gathered G rows + fused positive-dot:
// Gsel[w] = (E0[id] + muls[id] @ P)/3 ; Abf = bf16(Gsel * 5*log2e)
// scal[slot] += clip(5 * dot(Gsel[w], E[id]), -5, 5)
__global__ void k_gsel(const int* __restrict__ ids, const float* __restrict__ base0,
                       const float* __restrict__ muls, const float* __restrict__ P,
                       const float* __restrict__ E,
                       float* __restrict__ Gsel, __nv_bfloat16* __restrict__ Abf,
                       float* scal, int slot, int nids){
    __shared__ float part[8];
    int i = blockIdx.x*256 + threadIdx.x;
    int w = i >> 6, d = i & 63;
    int id = ids[w];
    float s = base0[(size_t)id*DIMV + d];
    #pragma unroll
    for (int r=0;r<RK;r++) s = fmaf(muls[(size_t)id*RK + r], P[r*DIMV + d], s);
    s *= (1.0f/3.0f);
    Gsel[i] = s;
    Abf[i] = __float2bfloat16(s * 7.2134752044448170f);  // (1/T) * log2(e)
    float prod = s * E[(size_t)id*DIMV + d];
    #pragma unroll
    for (int off=16; off>0; off>>=1) prod += __shfl_xor_sync(0xffffffffu, prod, off);
    if ((threadIdx.x & 31) == 0) part[threadIdx.x >> 5] = prod;
    __syncthreads();
    if (threadIdx.x < 4){
        float dsum = part[2*threadIdx.x] + part[2*threadIdx.x+1];
        float v = fminf(fmaxf(dsum*5.0f, -5.0f), 5.0f);
        atomicAdd(&scal[slot], v);
    }
}

__device__ __forceinline__ float ex2f(float x){
    float r;
    asm("ex2.approx.f32 %0, %1;" : "=f"(r) : "f"(x));
    return r;
}

// sums[m0+r] += sum_j exp2( dot(Abf[m0+r], Ebf[j]) )   (scale pre-folded into A)
// CTA tile: 128 ids x 128 cols, K=64 single shot. 8 warps = 4(M) x 2(N), warp 32x64.
__global__ void __launch_bounds__(256,2) k_negmma(
        const __nv_bfloat16* __restrict__ A, const __nv_bfloat16* __restrict__ E,
        int NJ, float* __restrict__ sums){
    __shared__ __nv_bfloat16 As[128][72];
    __shared__ __nv_bfloat16 Bs[128][72];
    __shared__ float ls[128];
    int tid = threadIdx.x;
    int m0 = blockIdx.y * 128;
    int jbase = blockIdx.x * 128;
    if (tid < 128) ls[tid] = 0.f;

    #pragma unroll
    for (int c = tid; c < 1024; c += 256){
        int r = c >> 3, c8 = c & 7;
        *(uint4*)&As[r][c8*8] = *(const uint4*)(A + (size_t)(m0 + r)*DIMV + c8*8);
        int j = jbase + r;
        uint4 v = make_uint4(0u,0u,0u,0u);
        if (j < NJ) v = *(const uint4*)(E + (size_t)j*DIMV + c8*8);
        *(uint4*)&Bs[r][c8*8] = v;
    }
    __syncthreads();

    int warp = tid >> 5, lane = tid & 31;
    int wm = warp >> 1, wn = warp & 1;
    int g = lane >> 2, t = lane & 3;

    float acc[2][8][4];
    #pragma unroll
    for (int mf=0;mf<2;mf++)
        #pragma unroll
        for (int nf=0;nf<8;nf++)
            #pragma unroll
            for (int q=0;q<4;q++) acc[mf][nf][q]=0.f;

    #pragma unroll
    for (int kk=0; kk<4; kk++){
        int kb = kk*16 + 2*t;
        unsigned a[2][4], b[8][2];
        #pragma unroll
        for (int mf=0; mf<2; mf++){
            int r = wm*32 + mf*16 + g;
            a[mf][0] = *(const unsigned*)&As[r  ][kb  ];
            a[mf][1] = *(const unsigned*)&As[r+8][kb  ];
            a[mf][2] = *(const unsigned*)&As[r  ][kb+8];
            a[mf][3] = *(const unsigned*)&As[r+8][kb+8];
        }
        #pragma unroll
        for (int nf=0; nf<8; nf++){
            int n = wn*64 + nf*8 + g;
            b[nf][0] = *(const unsigned*)&Bs[n][kb  ];
            b[nf][1] = *(const unsigned*)&Bs[n][kb+8];
        }
        #pragma unroll
        for (int mf=0; mf<2; mf++)
            #pragma unroll
            for (int nf=0; nf<8; nf++)
                asm volatile(
                    "mma.sync.aligned.m16n8k16.row.col.f32.bf16.bf16.f32 "
                    "{%0,%1,%2,%3}, {%4,%5,%6,%7}, {%8,%9}, {%0,%1,%2,%3};"
                    : "+f"(acc[mf][nf][0]), "+f"(acc[mf][nf][1]),
                      "+f"(acc[mf][nf][2]), "+f"(acc[mf][nf][3])
                    : "r"(a[mf][0]), "r"(a[mf][1]), "r"(a[mf][2]), "r"(a[mf][3]),
                      "r"(b[nf][0]), "r"(b[nf][1]));
    }

    // epilogue: exp2 + masked sum per row
    #pragma unroll
    for (int mf=0; mf<2; mf++){
        float s0 = 0.f, s1 = 0.f;
        #pragma unroll
        for (int nf=0; nf<8; nf++){
            int jc = jbase + wn*64 + nf*8 + 2*t;
            bool v0 = jc < NJ, v1 = (jc+1) < NJ;
            s0 += (v0 ? ex2f(acc[mf][nf][0]) : 0.f) + (v1 ? ex2f(acc[mf][nf][1]) : 0.f);
            s1 += (v0 ? ex2f(acc[mf][nf][2]) : 0.f) + (v1 ? ex2f(acc[mf][nf][3]) : 0.f);
        }
        s0 += __shfl_xor_sync(0xffffffffu, s0, 1);
        s0 += __shfl_xor_sync(0xffffffffu, s0, 2);
        s1 += __shfl_xor_sync(0xffffffffu, s1, 1);
        s1 += __shfl_xor_sync(0xffffffffu, s1, 2);
        if (t == 0){
            int rl = wm*32 + mf*16 + g;
            atomicAdd(&ls[rl],   s0);
            atomicAdd(&ls[rl+8], s1);
        }
    }
    __syncthreads();
    if (tid < 128) atomicAdd(&sums[m0 + tid], ls[tid]);
}

__global__ void k_out(const float* __restrict__ Eu, const float* __restrict__ Ei,
                      const float* __restrict__ iu, const float* __restrict__ tu,
                      const float* __restrict__ ii, const float* __restrict__ ti,
                      float* __restrict__ out){
    int row = blockIdx.x*8 + (threadIdx.x >> 5);
    int lane = threadIdx.x & 31;
    const float *e, *a, *b; float* o;
    if (row < NU){
        e = Eu + (size_t)row*DIMV; a = iu + (size_t)row*DIMV; b = tu + (size_t)row*DIMV;
        o = out + (size_t)row*DIMV;
    } else {
        int r = row - NU;
        e = Ei + (size_t)r*DIMV; a = ii + (size_t)r*DIMV; b = ti + (size_t)r*DIMV;
        o = out + (size_t)NU*DIMV + (size_t)r*DIMV;
    }
    float2 e2 = ((const float2*)e)[lane];
    float2 a2 = ((const float2*)a)[lane];
    float2 b2 = ((const float2*)b)[lane];
    float sa = a2.x*a2.x + a2.y*a2.y;
    float sb = b2.x*b2.x + b2.y*b2.y;
    for (int off=16; off>0; off>>=1){
        sa += __shfl_xor_sync(0xffffffffu, sa, off);
        sb += __shfl_xor_sync(0xffffffffu, sb, off);
    }
    float na = fmaxf(sqrtf(sa), 1e-12f);
    float nb = fmaxf(sqrtf(sb), 1e-12f);
    float2 r2;
    r2.x = e2.x + 0.02f*(a2.x/na) + 0.02f*(b2.x/nb);
    r2.y = e2.y + 0.02f*(a2.y/na) + 0.02f*(b2.y/nb);
    ((float2*)o)[lane] = r2;
}

__global__ void k_loss(const float* __restrict__ sumU, const float* __restrict__ sumI,
                       const float* __restrict__ scal, float* outp){
    __shared__ float sh[256];
    int tid = threadIdx.x;
    float acc = 0.f;
    for (int k=tid; k<NUID; k+=256) acc += logf(sumU[k]) * (1.0f/NUID);
    for (int k=tid; k<NIID; k+=256) acc += logf(sumI[k]) * (1.0f/NIID);
    sh[tid] = acc;
    __syncthreads();
    for (int off=128; off>0; off>>=1){
        if (tid < off) sh[tid] += sh[tid+off];
        __syncthreads();
    }
    if (tid == 0){
        float neg = sh[0];
        float pos = scal[0]*(1.0f/NUID) + scal[1]*(1.0f/NIID);
        outp[0] = (neg - pos) * 4.0f;   // * (len(G_u_list)+1)
    }
}

// ---------------- launcher ----------------
extern "C" void kernel_launch(void* const* d_in, const int* in_sizes, int n_in,
                              void* d_out, int out_size){
    const float* user_emb     = (const float*)d_in[0];
    const float* item_emb     = (const float*)d_in[1];
    const float* user_emb_pre = (const float*)d_in[2];
    const float* item_emb_pre = (const float*)d_in[3];
    const float* img_item     = (const float*)d_in[4];
    const float* txt_item     = (const float*)d_in[5];
    const float* img_user     = (const float*)d_in[6];
    const float* txt_user     = (const float*)d_in[7];
    const int*   arows        = (const int*)d_in[8];
    const int*   acols        = (const int*)d_in[9];
    const float* avals        = (const float*)d_in[10];
    const float* ut           = (const float*)d_in[11];
    const float* vt           = (const float*)d_in[12];
    const float* u_mul_s      = (const float*)d_in[13];
    const float* v_mul_s      = (const float*)d_in[14];
    const int*   uids         = (const int*)d_in[15];
    const int*   iids         = (const int*)d_in[16];
    float* out = (float*)d_out;

    float *Eu0,*Ei0,*Zu1,*Zi1,*Eu,*Ei,*GselU,*GselI,*P1,*P2,*sumU,*sumI,*scal;
    __nv_bfloat16 *E0bfU,*E0bfI,*Z1bfU,*Z1bfI,*EbfU,*EbfI,*AbfU,*AbfI;
    int *rcnt,*rbase,*rfill,*ccnt,*cbase,*cfill,*bsU,*bsI;
    int2 *redge,*cedge;
    cudaGetSymbolAddress((void**)&Eu0,  g_Eu0);
    cudaGetSymbolAddress((void**)&Ei0,  g_Ei0);
    cudaGetSymbolAddress((void**)&Zu1,  g_Zu1);
    cudaGetSymbolAddress((void**)&Zi1,  g_Zi1);
    cudaGetSymbolAddress((void**)&Eu,   g_Eu);
    cudaGetSymbolAddress((void**)&Ei,   g_Ei);
    cudaGetSymbolAddress((void**)&E0bfU,g_E0bfU);
    cudaGetSymbolAddress((void**)&E0bfI,g_E0bfI);
    cudaGetSymbolAddress((void**)&Z1bfU,g_Z1bfU);
    cudaGetSymbolAddress((void**)&Z1bfI,g_Z1bfI);
    cudaGetSymbolAddress((void**)&EbfU, g_EbfU);
    cudaGetSymbolAddress((void**)&EbfI, g_EbfI);
    cudaGetSymbolAddress((void**)&GselU,g_GselU);
    cudaGetSymbolAddress((void**)&GselI,g_GselI);
    cudaGetSymbolAddress((void**)&AbfU, g_AbfU);
    cudaGetSymbolAddress((void**)&AbfI, g_AbfI);
    cudaGetSymbolAddress((void**)&P1,   g_P1);
    cudaGetSymbolAddress((void**)&P2,   g_P2);
    cudaGetSymbolAddress((void**)&sumU, g_sumU);
    cudaGetSymbolAddress((void**)&sumI, g_sumI);
    cudaGetSymbolAddress((void**)&scal, g_scal);
    cudaGetSymbolAddress((void**)&rcnt, g_rcnt);
    cudaGetSymbolAddress((void**)&rbase,g_rbase);
    cudaGetSymbolAddress((void**)&rfill,g_rfill);
    cudaGetSymbolAddress((void**)&ccnt, g_ccnt);
    cudaGetSymbolAddress((void**)&cbase,g_cbase);
    cudaGetSymbolAddress((void**)&cfill,g_cfill);
    cudaGetSymbolAddress((void**)&redge,g_redge);
    cudaGetSymbolAddress((void**)&cedge,g_cedge);
    cudaGetSymbolAddress((void**)&bsU,  g_bsU);
    cudaGetSymbolAddress((void**)&bsI,  g_bsI);

    // init + CSR/CSC build
    k_setup<<<((NU+NI)*16+255)/256, 256>>>((const float4*)user_emb,(const float4*)user_emb_pre,
                                           (const float4*)item_emb,(const float4*)item_emb_pre,
                                           (float4*)Eu0,(float4*)Ei0,
                                           (uint2*)E0bfU,(uint2*)E0bfI,
                                           rcnt,rfill,ccnt,cfill,P1,P2,sumU,sumI,scal);
    k_count<<<(NNZE+255)/256, 256>>>(arows, acols, rcnt, ccnt);
    k_scan_block<<<98, 1024>>>(rcnt, NU, rbase, bsU);
    k_scan_top<<<1, 128>>>(bsU, 98);
    k_scan_add<<<98, 1024>>>(rbase, NU, bsU);
    k_scan_block<<<49, 1024>>>(ccnt, NI, cbase, bsI);
    k_scan_top<<<1, 128>>>(bsI, 49);
    k_scan_add<<<49, 1024>>>(cbase, NI, bsI);
    k_scatter<<<(NNZE+255)/256, 256>>>(arows,acols,avals, rbase,rfill,redge,
                                       cbase,cfill,cedge);

    // GNN layer 1 (bf16 gathers, fp32 accumulation; emit bf16 Z1)
    k_spmm<<<NU/16, 256>>>(rbase,rcnt,redge, E0bfI, nullptr,nullptr, 1.0f, Zu1, Z1bfU, NU);
    k_spmm<<<NI/16, 256>>>(cbase,ccnt,cedge, E0bfU, nullptr,nullptr, 1.0f, Zi1, Z1bfI, NI);
    // GNN layer 2 fused with averaging: E = (E0 + Z1 + Z2)/3, also emit bf16
    k_spmm<<<NU/16, 256>>>(rbase,rcnt,redge, Z1bfI, Eu0, Zu1, 1.0f/3.0f, Eu, EbfU, NU);
    k_spmm<<<NI/16, 256>>>(cbase,ccnt,cedge, Z1bfU, Ei0, Zi1, 1.0f/3.0f, Ei, EbfI, NI);

    // low-rank SVD path (only gathered G rows are needed downstream)
    k_lowrank<<<128, 256>>>(vt, Ei0, Zi1, P1, NI);
    k_lowrank<<<128, 256>>>(ut, Eu0, Zu1, P2, NU);
    // gsel + fused positive-dot
    k_gsel<<<(NUID*DIMV)/256, 256>>>(uids, Eu0, u_mul_s, P1, Eu, GselU, AbfU, scal, 0, NUID);
    k_gsel<<<(NIID*DIMV)/256, 256>>>(iids, Ei0, v_mul_s, P2, Ei, GselI, AbfI, scal, 1, NIID);

    // contrastive loss: tensor-core logsumexp GEMM
    k_negmma<<<dim3((NU+127)/128, NUID/128), 256>>>(AbfU, EbfU, NU, sumU);
    k_negmma<<<dim3((NI+127)/128, NIID/128), 256>>>(AbfI, EbfI, NI, sumI);

    // outputs
    k_out<<<(NU+NI)/8, 256>>>(Eu, Ei, img_user, txt_user, img_item, txt_item, out);
    k_loss<<<1, 256>>>(sumU, sumI, scal, out + (size_t)(NU+NI)*DIMV);
}

// round 6
// speedup vs baseline: 3.1198x; 1.0376x over previous
#include <cuda_runtime.h>
#include <cuda_bf16.h>
#include <math.h>

#define NU 100000
#define NI 50000
#define DIMV 64
#define RK 5
#define NNZE 2000000
#define NUID 2048
#define NIID 4096

// ---------------- device scratch (no allocations allowed) ----------------
__device__ __align__(16) float g_Eu0[NU*DIMV];
__device__ __align__(16) float g_Ei0[NI*DIMV];
__device__ __align__(16) float g_Zu1[NU*DIMV];
__device__ __align__(16) float g_Zi1[NI*DIMV];
__device__ __align__(16) float g_Eu [NU*DIMV];
__device__ __align__(16) float g_Ei [NI*DIMV];
__device__ __align__(16) __nv_bfloat16 g_E0bfU[NU*DIMV];
__device__ __align__(16) __nv_bfloat16 g_E0bfI[NI*DIMV];
__device__ __align__(16) __nv_bfloat16 g_Z1bfU[NU*DIMV];
__device__ __align__(16) __nv_bfloat16 g_Z1bfI[NI*DIMV];
__device__ __align__(16) __nv_bfloat16 g_EbfU[NU*DIMV];
__device__ __align__(16) __nv_bfloat16 g_EbfI[NI*DIMV];
__device__ __align__(16) float g_GselU[NUID*DIMV];
__device__ __align__(16) float g_GselI[NIID*DIMV];
__device__ __align__(16) __nv_bfloat16 g_AbfU[NUID*DIMV];
__device__ __align__(16) __nv_bfloat16 g_AbfI[NIID*DIMV];
__device__ float g_P1[RK*DIMV];
__device__ float g_P2[RK*DIMV];
__device__ int   g_rcnt[NU];
__device__ int   g_rbase[NU];
__device__ int   g_ccnt[NI];
__device__ int   g_cbase[NI];
__device__ __align__(16) int2 g_redge[NNZE];   // (col, val_bits)
__device__ __align__(16) int2 g_cedge[NNZE];   // (row, val_bits)
__device__ int   g_bsU[128];
__device__ int   g_bsI[128];
__device__ float g_sumU[NUID];
__device__ float g_sumI[NIID];
__device__ float g_scal[8];

__device__ __forceinline__ uint2 pack_bf4(float4 v){
    __nv_bfloat162 p0 = __floats2bfloat162_rn(v.x, v.y);
    __nv_bfloat162 p1 = __floats2bfloat162_rn(v.z, v.w);
    uint2 r;
    r.x = *(unsigned*)&p0;
    r.y = *(unsigned*)&p1;
    return r;
}

// ---------------- kernels ----------------

// fused zero + E0 init (fp32 + bf16 copies)
__global__ void k_setup(const float4* __restrict__ ue, const float4* __restrict__ uep,
                        const float4* __restrict__ ie, const float4* __restrict__ iep,
                        float4* __restrict__ Eu0, float4* __restrict__ Ei0,
                        uint2* __restrict__ E0bfU, uint2* __restrict__ E0bfI,
                        int* rcnt,int* ccnt,
                        float* P1,float* P2,float* sumU,float* sumI,float* scal){
    int i = blockIdx.x*256 + threadIdx.x;
    if (i < NU*16){
        float4 a = ue[i], b = uep[i];
        float4 s = make_float4(a.x+b.x, a.y+b.y, a.z+b.z, a.w+b.w);
        Eu0[i] = s;
        E0bfU[i] = pack_bf4(s);
    } else if (i < (NU+NI)*16){
        int k = i - NU*16;
        float4 a = ie[k], b = iep[k];
        float4 s = make_float4(a.x+b.x, a.y+b.y, a.z+b.z, a.w+b.w);
        Ei0[k] = s;
        E0bfI[k] = pack_bf4(s);
    }
    if (i < NU) rcnt[i]=0;
    if (i < NI) ccnt[i]=0;
    if (i < NUID) sumU[i]=0.f;
    if (i < NIID) sumI[i]=0.f;
    if (i < RK*DIMV){ P1[i]=0.f; P2[i]=0.f; }
    if (i < 8) scal[i]=0.f;
}

__global__ void k_count(const int* __restrict__ rows, const int* __restrict__ cols,
                        int* rcnt, int* ccnt){
    int e = blockIdx.x*256 + threadIdx.x;
    if (e < NNZE){
        atomicAdd(&rcnt[rows[e]], 1);
        atomicAdd(&ccnt[cols[e]], 1);
    }
}

// fused U/I block scan: blocks 0..97 -> rcnt, 98..146 -> ccnt
__global__ void k_scanb(const int* __restrict__ rcnt, int* rbase, int* bsU,
                        const int* __restrict__ ccnt, int* cbase, int* bsI){
    __shared__ int sh[1024];
    const int* cnt; int* base; int* bsums; int n, b;
    if (blockIdx.x < 98){ cnt=rcnt; base=rbase; bsums=bsU; n=NU; b=blockIdx.x; }
    else                { cnt=ccnt; base=cbase; bsums=bsI; n=NI; b=blockIdx.x-98; }
    int i = b*1024 + threadIdx.x;
    int v = (i < n) ? cnt[i] : 0;
    sh[threadIdx.x] = v;
    __syncthreads();
    for (int off=1; off<1024; off<<=1){
        int t = (threadIdx.x >= off) ? sh[threadIdx.x-off] : 0;
        __syncthreads();
        sh[threadIdx.x] += t;
        __syncthreads();
    }
    if (i < n) base[i] = sh[threadIdx.x] - v;
    if (threadIdx.x == 1023) bsums[b] = sh[1023];
}

// fused top scan: threads 0..127 scan bsU(98), 128..255 scan bsI(49)
__global__ void k_scant(int* bsU, int* bsI){
    __shared__ int sh[256];
    int tid = threadIdx.x;
    int seg = tid >> 7, l = tid & 127;
    int nb = seg ? 49 : 98;
    int* arr = seg ? bsI : bsU;
    int v = (l < nb) ? arr[l] : 0;
    sh[tid] = v;
    __syncthreads();
    for (int off=1; off<128; off<<=1){
        int t = (l >= off) ? sh[tid-off] : 0;
        __syncthreads();
        sh[tid] += t;
        __syncthreads();
    }
    if (l < nb) arr[l] = sh[tid] - v;
}

__global__ void k_scana(int* rbase, const int* __restrict__ bsU,
                        int* cbase, const int* __restrict__ bsI){
    int* base; const int* bsums; int n, b;
    if (blockIdx.x < 98){ base=rbase; bsums=bsU; n=NU; b=blockIdx.x; }
    else                { base=cbase; bsums=bsI; n=NI; b=blockIdx.x-98; }
    int i = b*1024 + threadIdx.x;
    if (i < n) base[i] += bsums[b];
}

// destructive scatter: after this, rbase[r] = row_end (= start + cnt)
__global__ void k_scatter(const int* __restrict__ rows, const int* __restrict__ cols,
                          const float* __restrict__ vals,
                          int* rbase, int2* redge, int* cbase, int2* cedge){
    int e = blockIdx.x*256 + threadIdx.x;
    if (e < NNZE){
        int r = rows[e], c = cols[e];
        int vb = __float_as_int(vals[e]);
        int pr = atomicAdd(&rbase[r], 1);
        redge[pr] = make_int2(c, vb);
        int pc = atomicAdd(&cbase[c], 1);
        cedge[pc] = make_int2(r, vb);
    }
}

// gather-style SpMM with bf16 source rows (fp32 accumulation).
// Edge handling: each 16-lane group loads 16 edges coalesced, shfl-broadcasts
// each -> 16 independent row-gathers in flight (MLP ~16).
// dst[row] = (sum_e v*srcbf[nbr] + add0[row] + add1[row]) * scale
// If outp != null: fused epilogue out = dst + 0.02*l2n(img) + 0.02*l2n(txt).
__global__ void k_spmm(const int* __restrict__ base, const int* __restrict__ cnt,
                       const int2* __restrict__ edges,
                       const __nv_bfloat16* __restrict__ srcbf,
                       const float* __restrict__ add0, const float* __restrict__ add1,
                       float scale, float* __restrict__ dst,
                       __nv_bfloat16* __restrict__ bdst,
                       const float* __restrict__ img, const float* __restrict__ txt,
                       float* __restrict__ outp, int nrows){
    int row = blockIdx.x*16 + (threadIdx.x >> 4);
    int lane = threadIdx.x & 15;
    if (row >= nrows) return;
    unsigned gmask = 0xffffu << (threadIdx.x & 16);
    int n = cnt[row];
    int s = base[row] - n;     // base was advanced to row_end by scatter
    float4 acc = make_float4(0.f,0.f,0.f,0.f);
    const uint2* s2 = (const uint2*)srcbf;
    int nb = n & ~15;
    for (int p = 0; p < nb; p += 16){
        int2 my = edges[s + p + lane];
        #pragma unroll
        for (int q=0;q<16;q++){
            int col = __shfl_sync(gmask, my.x, q, 16);
            float v = __int_as_float(__shfl_sync(gmask, my.y, q, 16));
            uint2 qv = s2[(size_t)col*16 + lane];
            float2 a = __bfloat1622float2(*(const __nv_bfloat162*)&qv.x);
            float2 b = __bfloat1622float2(*(const __nv_bfloat162*)&qv.y);
            acc.x = fmaf(v, a.x, acc.x);
            acc.y = fmaf(v, a.y, acc.y);
            acc.z = fmaf(v, b.x, acc.z);
            acc.w = fmaf(v, b.y, acc.w);
        }
    }
    int rem = n - nb;
    if (rem > 0){
        int2 my = (lane < rem) ? edges[s + nb + lane] : make_int2(0,0);
        for (int q=0;q<rem;q++){
            int col = __shfl_sync(gmask, my.x, q, 16);
            float v = __int_as_float(__shfl_sync(gmask, my.y, q, 16));
            uint2 qv = s2[(size_t)col*16 + lane];
            float2 a = __bfloat1622float2(*(const __nv_bfloat162*)&qv.x);
            float2 b = __bfloat1622float2(*(const __nv_bfloat162*)&qv.y);
            acc.x = fmaf(v, a.x, acc.x);
            acc.y = fmaf(v, a.y, acc.y);
            acc.z = fmaf(v, b.x, acc.z);
            acc.w = fmaf(v, b.y, acc.w);
        }
    }
    size_t o = (size_t)row*16 + lane;
    if (add0){ float4 a = ((const float4*)add0)[o]; acc.x+=a.x; acc.y+=a.y; acc.z+=a.z; acc.w+=a.w; }
    if (add1){ float4 a = ((const float4*)add1)[o]; acc.x+=a.x; acc.y+=a.y; acc.z+=a.z; acc.w+=a.w; }
    acc.x*=scale; acc.y*=scale; acc.z*=scale; acc.w*=scale;
    ((float4*)dst)[o] = acc;
    if (bdst) ((uint2*)bdst)[o] = pack_bf4(acc);
    if (outp){
        float4 a4 = ((const float4*)img)[o];
        float4 b4 = ((const float4*)txt)[o];
        float sa = a4.x*a4.x + a4.y*a4.y + a4.z*a4.z + a4.w*a4.w;
        float sb = b4.x*b4.x + b4.y*b4.y + b4.z*b4.z + b4.w*b4.w;
        #pragma unroll
        for (int off=8; off>0; off>>=1){
            sa += __shfl_xor_sync(gmask, sa, off, 16);
            sb += __shfl_xor_sync(gmask, sb, off, 16);
        }
        float na = fmaxf(sqrtf(sa), 1e-12f);
        float nb2 = fmaxf(sqrtf(sb), 1e-12f);
        float4 r;
        r.x = acc.x + 0.02f*(a4.x/na) + 0.02f*(b4.x/nb2);
        r.y = acc.y + 0.02f*(a4.y/na) + 0.02f*(b4.y/nb2);
        r.z = acc.z + 0.02f*(a4.z/na) + 0.02f*(b4.z/nb2);
        r.w = acc.w + 0.02f*(a4.w/na) + 0.02f*(b4.w/nb2);
        ((float4*)outp)[o] = r;
    }
}

// P[r][d] += sum_i fac[r*n+i] * (A[i][d] + B[i][d])
__global__ void k_lowrank(const float* __restrict__ fac, const float* __restrict__ A,
                          const float* __restrict__ B, float* __restrict__ P, int n){
    int d  = threadIdx.x & 63;
    int il = threadIdx.x >> 6;   // 0..3
    int chunk = (n + gridDim.x - 1) / gridDim.x;
    int i0 = blockIdx.x*chunk;
    int i1 = min(i0 + chunk, n);
    float acc[RK];
    #pragma unroll
    for (int r=0;r<RK;r++) acc[r]=0.f;
    for (int i=i0+il; i<i1; i+=4){
        float m = A[(size_t)i*DIMV + d] + B[(size_t)i*DIMV + d];
        #pragma unroll
        for (int r=0;r<RK;r++) acc[r] = fmaf(fac[(size_t)r*n + i], m, acc[r]);
    }
    __shared__ float red[4][RK][DIMV];
    #pragma unroll
    for (int r=0;r<RK;r++) red[il][r][d] = acc[r];
    __syncthreads();
    if (il == 0){
        #pragma unroll
        for (int r=0;r<RK;r++){
            float t = red[0][r][d] + red[1][r][d] + red[2][r][d] + red[3][r][d];
            atomicAdd(&P[r*DIMV + d], t);
        }
    }
}

// gathered G rows + fused positive-dot
__global__ void k_gsel(const int* __restrict__ ids, const float* __restrict__ base0,
                       const float* __restrict__ muls, const float* __restrict__ P,
                       const float* __restrict__ E,
                       float* __restrict__ Gsel, __nv_bfloat16* __restrict__ Abf,
                       float* scal, int slot, int nids){
    __shared__ float part[8];
    int i = blockIdx.x*256 + threadIdx.x;
    int w = i >> 6, d = i & 63;
    int id = ids[w];
    float s = base0[(size_t)id*DIMV + d];
    #pragma unroll
    for (int r=0;r<RK;r++) s = fmaf(muls[(size_t)id*RK + r], P[r*DIMV + d], s);
    s *= (1.0f/3.0f);
    Gsel[i] = s;
    Abf[i] = __float2bfloat16(s * 7.2134752044448170f);  // (1/T) * log2(e)
    float prod = s * E[(size_t)id*DIMV + d];
    #pragma unroll
    for (int off=16; off>0; off>>=1) prod += __shfl_xor_sync(0xffffffffu, prod, off);
    if ((threadIdx.x & 31) == 0) part[threadIdx.x >> 5] = prod;
    __syncthreads();
    if (threadIdx.x < 4){
        float dsum = part[2*threadIdx.x] + part[2*threadIdx.x+1];
        float v = fminf(fmaxf(dsum*5.0f, -5.0f), 5.0f);
        atomicAdd(&scal[slot], v);
    }
}

__device__ __forceinline__ float ex2f(float x){
    float r;
    asm("ex2.approx.f32 %0, %1;" : "=f"(r) : "f"(x));
    return r;
}

// sums[m0+r] += sum_j exp2( dot(Abf[m0+r], Ebf[j]) )
__global__ void __launch_bounds__(256,2) k_negmma(
        const __nv_bfloat16* __restrict__ A, const __nv_bfloat16* __restrict__ E,
        int NJ, float* __restrict__ sums){
    __shared__ __nv_bfloat16 As[128][72];
    __shared__ __nv_bfloat16 Bs[128][72];
    __shared__ float ls[128];
    int tid = threadIdx.x;
    int m0 = blockIdx.y * 128;
    int jbase = blockIdx.x * 128;
    if (tid < 128) ls[tid] = 0.f;

    #pragma unroll
    for (int c = tid; c < 1024; c += 256){
        int r = c >> 3, c8 = c & 7;
        *(uint4*)&As[r][c8*8] = *(const uint4*)(A + (size_t)(m0 + r)*DIMV + c8*8);
        int j = jbase + r;
        uint4 v = make_uint4(0u,0u,0u,0u);
        if (j < NJ) v = *(const uint4*)(E + (size_t)j*DIMV + c8*8);
        *(uint4*)&Bs[r][c8*8] = v;
    }
    __syncthreads();

    int warp = tid >> 5, lane = tid & 31;
    int wm = warp >> 1, wn = warp & 1;
    int g = lane >> 2, t = lane & 3;

    float acc[2][8][4];
    #pragma unroll
    for (int mf=0;mf<2;mf++)
        #pragma unroll
        for (int nf=0;nf<8;nf++)
            #pragma unroll
            for (int q=0;q<4;q++) acc[mf][nf][q]=0.f;

    #pragma unroll
    for (int kk=0; kk<4; kk++){
        int kb = kk*16 + 2*t;
        unsigned a[2][4], b[8][2];
        #pragma unroll
        for (int mf=0; mf<2; mf++){
            int r = wm*32 + mf*16 + g;
            a[mf][0] = *(const unsigned*)&As[r  ][kb  ];
            a[mf][1] = *(const unsigned*)&As[r+8][kb  ];
            a[mf][2] = *(const unsigned*)&As[r  ][kb+8];
            a[mf][3] = *(const unsigned*)&As[r+8][kb+8];
        }
        #pragma unroll
        for (int nf=0; nf<8; nf++){
            int n = wn*64 + nf*8 + g;
            b[nf][0] = *(const unsigned*)&Bs[n][kb  ];
            b[nf][1] = *(const unsigned*)&Bs[n][kb+8];
        }
        #pragma unroll
        for (int mf=0; mf<2; mf++)
            #pragma unroll
            for (int nf=0; nf<8; nf++)
                asm volatile(
                    "mma.sync.aligned.m16n8k16.row.col.f32.bf16.bf16.f32 "
                    "{%0,%1,%2,%3}, {%4,%5,%6,%7}, {%8,%9}, {%0,%1,%2,%3};"
                    : "+f"(acc[mf][nf][0]), "+f"(acc[mf][nf][1]),
                      "+f"(acc[mf][nf][2]), "+f"(acc[mf][nf][3])
                    : "r"(a[mf][0]), "r"(a[mf][1]), "r"(a[mf][2]), "r"(a[mf][3]),
                      "r"(b[nf][0]), "r"(b[nf][1]));
    }

    #pragma unroll
    for (int mf=0; mf<2; mf++){
        float s0 = 0.f, s1 = 0.f;
        #pragma unroll
        for (int nf=0; nf<8; nf++){
            int jc = jbase + wn*64 + nf*8 + 2*t;
            bool v0 = jc < NJ, v1 = (jc+1) < NJ;
            s0 += (v0 ? ex2f(acc[mf][nf][0]) : 0.f) + (v1 ? ex2f(acc[mf][nf][1]) : 0.f);
            s1 += (v0 ? ex2f(acc[mf][nf][2]) : 0.f) + (v1 ? ex2f(acc[mf][nf][3]) : 0.f);
        }
        s0 += __shfl_xor_sync(0xffffffffu, s0, 1);
        s0 += __shfl_xor_sync(0xffffffffu, s0, 2);
        s1 += __shfl_xor_sync(0xffffffffu, s1, 1);
        s1 += __shfl_xor_sync(0xffffffffu, s1, 2);
        if (t == 0){
            int rl = wm*32 + mf*16 + g;
            atomicAdd(&ls[rl],   s0);
            atomicAdd(&ls[rl+8], s1);
        }
    }
    __syncthreads();
    if (tid < 128) atomicAdd(&sums[m0 + tid], ls[tid]);
}

__global__ void k_loss(const float* __restrict__ sumU, const float* __restrict__ sumI,
                       const float* __restrict__ scal, float* outp){
    __shared__ float sh[256];
    int tid = threadIdx.x;
    float acc = 0.f;
    for (int k=tid; k<NUID; k+=256) acc += logf(sumU[k]) * (1.0f/NUID);
    for (int k=tid; k<NIID; k+=256) acc += logf(sumI[k]) * (1.0f/NIID);
    sh[tid] = acc;
    __syncthreads();
    for (int off=128; off>0; off>>=1){
        if (tid < off) sh[tid] += sh[tid+off];
        __syncthreads();
    }
    if (tid == 0){
        float neg = sh[0];
        float pos = scal[0]*(1.0f/NUID) + scal[1]*(1.0f/NIID);
        outp[0] = (neg - pos) * 4.0f;
    }
}

// ---------------- launcher ----------------
extern "C" void kernel_launch(void* const* d_in, const int* in_sizes, int n_in,
                              void* d_out, int out_size){
    const float* user_emb     = (const float*)d_in[0];
    const float* item_emb     = (const float*)d_in[1];
    const float* user_emb_pre = (const float*)d_in[2];
    const float* item_emb_pre = (const float*)d_in[3];
    const float* img_item     = (const float*)d_in[4];
    const float* txt_item     = (const float*)d_in[5];
    const float* img_user     = (const float*)d_in[6];
    const float* txt_user     = (const float*)d_in[7];
    const int*   arows        = (const int*)d_in[8];
    const int*   acols        = (const int*)d_in[9];
    const float* avals        = (const float*)d_in[10];
    const float* ut           = (const float*)d_in[11];
    const float* vt           = (const float*)d_in[12];
    const float* u_mul_s      = (const float*)d_in[13];
    const float* v_mul_s      = (const float*)d_in[14];
    const int*   uids         = (const int*)d_in[15];
    const int*   iids         = (const int*)d_in[16];
    float* out = (float*)d_out;

    float *Eu0,*Ei0,*Zu1,*Zi1,*Eu,*Ei,*GselU,*GselI,*P1,*P2,*sumU,*sumI,*scal;
    __nv_bfloat16 *E0bfU,*E0bfI,*Z1bfU,*Z1bfI,*EbfU,*EbfI,*AbfU,*AbfI;
    int *rcnt,*rbase,*ccnt,*cbase,*bsU,*bsI;
    int2 *redge,*cedge;
    cudaGetSymbolAddress((void**)&Eu0,  g_Eu0);
    cudaGetSymbolAddress((void**)&Ei0,  g_Ei0);
    cudaGetSymbolAddress((void**)&Zu1,  g_Zu1);
    cudaGetSymbolAddress((void**)&Zi1,  g_Zi1);
    cudaGetSymbolAddress((void**)&Eu,   g_Eu);
    cudaGetSymbolAddress((void**)&Ei,   g_Ei);
    cudaGetSymbolAddress((void**)&E0bfU,g_E0bfU);
    cudaGetSymbolAddress((void**)&E0bfI,g_E0bfI);
    cudaGetSymbolAddress((void**)&Z1bfU,g_Z1bfU);
    cudaGetSymbolAddress((void**)&Z1bfI,g_Z1bfI);
    cudaGetSymbolAddress((void**)&EbfU, g_EbfU);
    cudaGetSymbolAddress((void**)&EbfI, g_EbfI);
    cudaGetSymbolAddress((void**)&GselU,g_GselU);
    cudaGetSymbolAddress((void**)&GselI,g_GselI);
    cudaGetSymbolAddress((void**)&AbfU, g_AbfU);
    cudaGetSymbolAddress((void**)&AbfI, g_AbfI);
    cudaGetSymbolAddress((void**)&P1,   g_P1);
    cudaGetSymbolAddress((void**)&P2,   g_P2);
    cudaGetSymbolAddress((void**)&sumU, g_sumU);
    cudaGetSymbolAddress((void**)&sumI, g_sumI);
    cudaGetSymbolAddress((void**)&scal, g_scal);
    cudaGetSymbolAddress((void**)&rcnt, g_rcnt);
    cudaGetSymbolAddress((void**)&rbase,g_rbase);
    cudaGetSymbolAddress((void**)&ccnt, g_ccnt);
    cudaGetSymbolAddress((void**)&cbase,g_cbase);
    cudaGetSymbolAddress((void**)&redge,g_redge);
    cudaGetSymbolAddress((void**)&cedge,g_cedge);
    cudaGetSymbolAddress((void**)&bsU,  g_bsU);
    cudaGetSymbolAddress((void**)&bsI,  g_bsI);

    // 1: init
    k_setup<<<((NU+NI)*16+255)/256, 256>>>((const float4*)user_emb,(const float4*)user_emb_pre,
                                           (const float4*)item_emb,(const float4*)item_emb_pre,
                                           (float4*)Eu0,(float4*)Ei0,
                                           (uint2*)E0bfU,(uint2*)E0bfI,
                                           rcnt,ccnt,P1,P2,sumU,sumI,scal);
    // 2: degree count
    k_count<<<(NNZE+255)/256, 256>>>(arows, acols, rcnt, ccnt);
    // 3-5: fused scans
    k_scanb<<<147, 1024>>>(rcnt, rbase, bsU, ccnt, cbase, bsI);
    k_scant<<<1, 256>>>(bsU, bsI);
    k_scana<<<147, 1024>>>(rbase, bsU, cbase, bsI);
    // 6: scatter (destructive: bases advance to row ends)
    k_scatter<<<(NNZE+255)/256, 256>>>(arows,acols,avals, rbase,redge, cbase,cedge);

    // 7-8: GNN layer 1 (bf16 gathers, fp32 accumulation; emit bf16 Z1)
    k_spmm<<<NU/16, 256>>>(rbase,rcnt,redge, E0bfI, nullptr,nullptr, 1.0f, Zu1, Z1bfU,
                           nullptr,nullptr,nullptr, NU);
    k_spmm<<<NI/16, 256>>>(cbase,ccnt,cedge, E0bfU, nullptr,nullptr, 1.0f, Zi1, Z1bfI,
                           nullptr,nullptr,nullptr, NI);
    // 9-10: GNN layer 2 + averaging + fused output epilogue
    k_spmm<<<NU/16, 256>>>(rbase,rcnt,redge, Z1bfI, Eu0, Zu1, 1.0f/3.0f, Eu, EbfU,
                           img_user, txt_user, out, NU);
    k_spmm<<<NI/16, 256>>>(cbase,ccnt,cedge, Z1bfU, Ei0, Zi1, 1.0f/3.0f, Ei, EbfI,
                           img_item, txt_item, out + (size_t)NU*DIMV, NI);

    // low-rank SVD path
    k_lowrank<<<128, 256>>>(vt, Ei0, Zi1, P1, NI);
    k_lowrank<<<128, 256>>>(ut, Eu0, Zu1, P2, NU);
    k_gsel<<<(NUID*DIMV)/256, 256>>>(uids, Eu0, u_mul_s, P1, Eu, GselU, AbfU, scal, 0, NUID);
    k_gsel<<<(NIID*DIMV)/256, 256>>>(iids, Ei0, v_mul_s, P2, Ei, GselI, AbfI, scal, 1, NIID);

    // contrastive loss: tensor-core logsumexp GEMM
    k_negmma<<<dim3((NU+127)/128, NUID/128), 256>>>(AbfU, EbfU, NU, sumU);
    k_negmma<<<dim3((NI+127)/128, NIID/128), 256>>>(AbfI, EbfI, NI, sumI);

    k_loss<<<1, 256>>>(sumU, sumI, scal, out + (size_t)(NU+NI)*DIMV);
}